// round 14
// baseline (speedup 1.0000x reference)
#include <cuda_runtime.h>
#include <math.h>

// Problem constants
#define BB     4
#define NQ     1024
#define NKK    1024
#define RDIM   256
#define NHH    8
#define DHEAD  64
#define BH     (BB*NHH)      // 32
#define OPROJ  (NHH*DHEAD)   // 512

typedef unsigned long long u64;

// ---- Blackwell packed f32x2 helpers (PTX 8.6+, sm_100+) ----
__device__ __forceinline__ u64 pk2(float lo, float hi) {
    u64 r; asm("mov.b64 %0, {%1, %2};" : "=l"(r) : "f"(lo), "f"(hi)); return r;
}
__device__ __forceinline__ u64 dup2(float v) { return pk2(v, v); }
__device__ __forceinline__ void up2(u64 v, float& lo, float& hi) {
    asm("mov.b64 {%0, %1}, %2;" : "=f"(lo), "=f"(hi) : "l"(v));
}
#define FMA2(acc, a, b) asm("fma.rn.f32x2 %0, %1, %2, %0;" : "+l"(acc) : "l"(a), "l"(b))
#define MUL2(d, a, b)   asm("mul.rn.f32x2 %0, %1, %2;"     : "=l"(d)   : "l"(a), "l"(b))

// ---------------- scratch (static device globals; no allocations) ----------------
__device__ __align__(256) float g_Qpr[BH*NQ*DHEAD];
__device__ __align__(256) float g_Qpi[BH*NQ*DHEAD];
__device__ __align__(256) float g_Kpr[BH*NKK*DHEAD];
__device__ __align__(256) float g_Kpi[BH*NKK*DHEAD];
__device__ __align__(256) float g_Vpr[BH*NKK*DHEAD];
__device__ __align__(256) float g_Vpi[BH*NKK*DHEAD];
__device__ __align__(256) float g_Ar [BB*NQ*OPROJ];
__device__ __align__(256) float g_Ai [BB*NQ*OPROJ];
__device__ __align__(256) float g_maskb[BB*NKK];

// ---------------- mask sniff + convert (uint8 / int32 / f32 / bf16) ----------------
__global__ void mask_kernel(const unsigned char* __restrict__ mp, int present) {
    __shared__ int s_flags;
    if (threadIdx.x == 0) s_flags = 0;
    __syncthreads();
    if (!present) {
        for (int k = threadIdx.x; k < BB*NKK; k += blockDim.x) g_maskb[k] = 0.0f;
        return;
    }
    int f = 0;
    for (int i = threadIdx.x; i < BB*NKK; i += blockDim.x) {
        unsigned char v = mp[i];
        if (v) {
            int p = i & 3;
            if (v == 0x3F)      { if (p == 1) f |= 2;  else if (p == 3) f |= 4;  else f |= 1; }
            else if (v == 0x80) { if (p == 0) f |= 8;  else if (p == 2) f |= 16; else f |= 1; }
            else                { if (p != 0) f |= 1;  else f |= 32; }
        }
    }
    if (f) atomicOr(&s_flags, f);
    __syncthreads();
    int F = s_flags;
    int mode;
    if      (F & (2|8))  mode = 3;
    else if (F & (4|16)) mode = 2;
    else if (F & 1)      mode = 0;
    else if (F & 32)     mode = 1;
    else                 mode = 0;

    for (int k = threadIdx.x; k < BB*NKK; k += blockDim.x) {
        bool m;
        if      (mode == 0) m = mp[k] != 0;
        else if (mode == 1) m = ((const int*)mp)[k] != 0;
        else if (mode == 2) m = ((const float*)mp)[k] != 0.0f;
        else                m = ((const unsigned short*)mp)[k] != 0;
        g_maskb[k] = m ? 0.0f : -1e30f;
    }
}

// ---------------- complex GEMM v3: double-buffered, transposed tiles, f32x2 FMA ----------------
// out = X @ W^T, X:(M,K) W:(N,K), complex. Accumulators packed over adjacent m rows.
#define TP 68
template<bool REAL_ONLY>
__global__ __launch_bounds__(256) void cgemm_kernel(
    const float* __restrict__ Xr, const float* __restrict__ Xi,
    const float* __restrict__ Wr, const float* __restrict__ Wi,
    float* __restrict__ Oc, int M, int N, int K, int which)
{
    __shared__ float Xs_r[2][16][TP], Xs_i[2][16][TP];
    __shared__ float Ws_r[2][16][TP], Ws_i[2][16][TP];

    float* Or = nullptr; float* Oi = nullptr;
    if (which == 0)      { Or = g_Qpr; Oi = g_Qpi; }
    else if (which == 1) { Or = g_Kpr; Oi = g_Kpi; }
    else if (which == 2) { Or = g_Vpr; Oi = g_Vpi; }
    else                 { Xr = g_Ar;  Xi = g_Ai;  }

    int tid = threadIdx.x;
    int tx = tid & 15, ty = tid >> 4;
    int m0 = blockIdx.y * 64, n0 = blockIdx.x * 64;
    int lrow = tid >> 2, lc = (tid & 3) * 4;

    // cre2[p][j] = packed (cre[2p][j], cre[2p+1][j])
    u64 cre2[2][4], cim2[2][4];
#pragma unroll
    for (int p = 0; p < 2; p++)
#pragma unroll
        for (int j = 0; j < 4; j++) { cre2[p][j] = 0ULL; cim2[p][j] = 0ULL; }

    const float* xr_p = Xr + (size_t)(m0 + lrow) * K + lc;
    const float* xi_p = Xi + (size_t)(m0 + lrow) * K + lc;
    const float* wr_p = Wr + (size_t)(n0 + lrow) * K + lc;
    const float* wi_p = Wi + (size_t)(n0 + lrow) * K + lc;

    int NK = K >> 4;

    float4 xr = *(const float4*)(xr_p);
    float4 xi = *(const float4*)(xi_p);
    float4 wr = *(const float4*)(wr_p);
    float4 wi = *(const float4*)(wi_p);
    {
        float xrv[4] = {xr.x,xr.y,xr.z,xr.w}, xiv[4] = {xi.x,xi.y,xi.z,xi.w};
        float wrv[4] = {wr.x,wr.y,wr.z,wr.w}, wiv[4] = {wi.x,wi.y,wi.z,wi.w};
#pragma unroll
        for (int c = 0; c < 4; c++) {
            Xs_r[0][lc+c][lrow] = xrv[c];
            Xs_i[0][lc+c][lrow] = xiv[c];
            Ws_r[0][lc+c][lrow] = wrv[c];
            Ws_i[0][lc+c][lrow] = wiv[c];
        }
    }
    __syncthreads();

    int pb = 0;
    for (int kt = 0; kt < NK; kt++) {
        if (kt + 1 < NK) {
            int k0 = (kt + 1) << 4;
            xr = *(const float4*)(xr_p + k0);
            xi = *(const float4*)(xi_p + k0);
            wr = *(const float4*)(wr_p + k0);
            wi = *(const float4*)(wi_p + k0);
        }
#pragma unroll
        for (int kk = 0; kk < 16; kk++) {
            float4 a_r = *(const float4*)&Xs_r[pb][kk][ty*4];
            float4 a_i = *(const float4*)&Xs_i[pb][kk][ty*4];
            float4 b_r = *(const float4*)&Ws_r[pb][kk][tx*4];
            float4 b_i = *(const float4*)&Ws_i[pb][kk][tx*4];
            u64 ar01 = pk2(a_r.x, a_r.y), ar23 = pk2(a_r.z, a_r.w);
            u64 ai01 = pk2(a_i.x, a_i.y), ai23 = pk2(a_i.z, a_i.w);
            float brv[4] = {b_r.x,b_r.y,b_r.z,b_r.w};
            float biv[4] = {b_i.x,b_i.y,b_i.z,b_i.w};
#pragma unroll
            for (int j = 0; j < 4; j++) {
                u64 brd  = dup2(brv[j]);
                u64 nbid = dup2(-biv[j]);
                FMA2(cre2[0][j], ar01, brd);
                FMA2(cre2[0][j], ai01, nbid);
                FMA2(cre2[1][j], ar23, brd);
                FMA2(cre2[1][j], ai23, nbid);
                if (!REAL_ONLY) {
                    u64 bid = dup2(biv[j]);
                    FMA2(cim2[0][j], ar01, bid);
                    FMA2(cim2[0][j], ai01, brd);
                    FMA2(cim2[1][j], ar23, bid);
                    FMA2(cim2[1][j], ai23, brd);
                }
            }
        }
        __syncthreads();
        if (kt + 1 < NK) {
            float xrv[4] = {xr.x,xr.y,xr.z,xr.w}, xiv[4] = {xi.x,xi.y,xi.z,xi.w};
            float wrv[4] = {wr.x,wr.y,wr.z,wr.w}, wiv[4] = {wi.x,wi.y,wi.z,wi.w};
            int nb = pb ^ 1;
#pragma unroll
            for (int c = 0; c < 4; c++) {
                Xs_r[nb][lc+c][lrow] = xrv[c];
                Xs_i[nb][lc+c][lrow] = xiv[c];
                Ws_r[nb][lc+c][lrow] = wrv[c];
                Ws_i[nb][lc+c][lrow] = wiv[c];
            }
            __syncthreads();
        }
        pb ^= 1;
    }

    float cre[4][4], cim[4][4];
#pragma unroll
    for (int p = 0; p < 2; p++)
#pragma unroll
        for (int j = 0; j < 4; j++) {
            up2(cre2[p][j], cre[2*p][j], cre[2*p+1][j]);
            up2(cim2[p][j], cim[2*p][j], cim[2*p+1][j]);
        }

#pragma unroll
    for (int i = 0; i < 4; i++) {
        int m = m0 + ty*4 + i;
#pragma unroll
        for (int j = 0; j < 4; j++) {
            int o = n0 + tx*4 + j;
            if (which != 3) {
                int b = m >> 10, n = m & 1023;
                int h = o >> 6,  d = o & 63;
                size_t idx = ((size_t)(b*NHH + h) * NQ + n) * 64 + d;
                Or[idx] = cre[i][j];
                Oi[idx] = cim[i][j];
            } else if (REAL_ONLY) {
                Oc[(size_t)m * N + o] = cre[i][j];
            } else {
                size_t base = ((size_t)m * N + o) * 2;
                Oc[base] = cre[i][j]; Oc[base+1] = cim[i][j];
            }
        }
    }
}

// ---------------- fused attention v3: f32x2 packed scores ((re,im) pairs) + packed AV ----------------
#define SS 68
#define ATTN_SMEM ((640*SS + 64) * 4)   // 174,336 B

__global__ __launch_bounds__(256, 1) void attn_kernel() {
    extern __shared__ float sm[];
    float* Qr = sm;
    float* Qi = Qr + 128*SS;
    float* Kr = Qi + 128*SS;
    float* Ki = Kr + 64*SS;
    float* Vr = Ki + 64*SS;
    float* Vi = Vr + 64*SS;
    float* P  = Vi + 64*SS;
    float* Mb = P  + 128*SS;

    int tid = threadIdx.x;
    int bh  = blockIdx.y;
    int b   = bh >> 3;
    int h   = bh & 7;
    int q0  = blockIdx.x * 128;

    int qa = tid >> 2;
    int qb = qa + 64;
    int l4 = tid & 3;

    const float* Qpr = g_Qpr + ((size_t)bh * NQ + q0) * 64;
    const float* Qpi = g_Qpi + ((size_t)bh * NQ + q0) * 64;
    for (int t = tid; t < 128*16; t += 256) {
        int r = t >> 4, c = (t & 15) * 4;
        *(float4*)(Qr + r*SS + c) = *(const float4*)(Qpr + r*64 + c);
        *(float4*)(Qi + r*SS + c) = *(const float4*)(Qpi + r*64 + c);
    }

    const float* Kbr = g_Kpr + (size_t)bh * NKK * 64;
    const float* Kbi = g_Kpi + (size_t)bh * NKK * 64;
    const float* Vbr = g_Vpr + (size_t)bh * NKK * 64;
    const float* Vbi = g_Vpi + (size_t)bh * NKK * 64;

    float mrunA = -1e30f, lrunA = 0.f;
    float mrunB = -1e30f, lrunB = 0.f;
    // AV accumulators: packed adjacent-d pairs. arA[2j],arA[2j+1] cover d = l4*4+j*16 .. +3
    u64 arA[8], aiA[8], arB[8], aiB[8];
#pragma unroll
    for (int i = 0; i < 8; i++) { arA[i]=0ULL; aiA[i]=0ULL; arB[i]=0ULL; aiB[i]=0ULL; }

    for (int kt = 0; kt < NKK/64; kt++) {
        int k0 = kt * 64;
        __syncthreads();
        for (int t = tid; t < 64*16; t += 256) {
            int r = t >> 4, c = (t & 15) * 4;
            *(float4*)(Kr + r*SS + c) = *(const float4*)(Kbr + (size_t)(k0+r)*64 + c);
            *(float4*)(Ki + r*SS + c) = *(const float4*)(Kbi + (size_t)(k0+r)*64 + c);
            *(float4*)(Vr + r*SS + c) = *(const float4*)(Vbr + (size_t)(k0+r)*64 + c);
            *(float4*)(Vi + r*SS + c) = *(const float4*)(Vbi + (size_t)(k0+r)*64 + c);
        }
        if (tid < 64) Mb[tid] = g_maskb[b*NKK + k0 + tid];
        __syncthreads();

        // ---- scores: accumulator = packed (s_re, s_im); 2 FMA2 per d-element per (q,k)
        u64 sA[16], sB[16];
#pragma unroll
        for (int j = 0; j < 16; j++) { sA[j] = 0ULL; sB[j] = 0ULL; }
#pragma unroll 2
        for (int d4 = 0; d4 < 16; d4++) {
            float4 qrA = *(float4*)(Qr + qa*SS + d4*4);
            float4 qiA = *(float4*)(Qi + qa*SS + d4*4);
            float4 qrB = *(float4*)(Qr + qb*SS + d4*4);
            float4 qiB = *(float4*)(Qi + qb*SS + d4*4);
            // aX[c] = (qr_c, qi_c) pairs with dup(kr): (qr*kr, qi*kr)  -> (re+, im+)
            // bX[c] = (qi_c,-qr_c) pairs with dup(ki): (qi*ki,-qr*ki) -> (re+, im+)
            u64 aA[4], bA[4], aB[4], bB[4];
            aA[0]=pk2(qrA.x,qiA.x); bA[0]=pk2(qiA.x,-qrA.x);
            aA[1]=pk2(qrA.y,qiA.y); bA[1]=pk2(qiA.y,-qrA.y);
            aA[2]=pk2(qrA.z,qiA.z); bA[2]=pk2(qiA.z,-qrA.z);
            aA[3]=pk2(qrA.w,qiA.w); bA[3]=pk2(qiA.w,-qrA.w);
            aB[0]=pk2(qrB.x,qiB.x); bB[0]=pk2(qiB.x,-qrB.x);
            aB[1]=pk2(qrB.y,qiB.y); bB[1]=pk2(qiB.y,-qrB.y);
            aB[2]=pk2(qrB.z,qiB.z); bB[2]=pk2(qiB.z,-qrB.z);
            aB[3]=pk2(qrB.w,qiB.w); bB[3]=pk2(qiB.w,-qrB.w);
#pragma unroll
            for (int j = 0; j < 16; j++) {
                int k = l4 + j*4;
                float4 kr = *(float4*)(Kr + k*SS + d4*4);
                float4 ki = *(float4*)(Ki + k*SS + d4*4);
                u64 kd;
                kd = dup2(kr.x); FMA2(sA[j], aA[0], kd); FMA2(sB[j], aB[0], kd);
                kd = dup2(kr.y); FMA2(sA[j], aA[1], kd); FMA2(sB[j], aB[1], kd);
                kd = dup2(kr.z); FMA2(sA[j], aA[2], kd); FMA2(sB[j], aB[2], kd);
                kd = dup2(kr.w); FMA2(sA[j], aA[3], kd); FMA2(sB[j], aB[3], kd);
                kd = dup2(ki.x); FMA2(sA[j], bA[0], kd); FMA2(sB[j], bB[0], kd);
                kd = dup2(ki.y); FMA2(sA[j], bA[1], kd); FMA2(sB[j], bB[1], kd);
                kd = dup2(ki.z); FMA2(sA[j], bA[2], kd); FMA2(sB[j], bB[2], kd);
                kd = dup2(ki.w); FMA2(sA[j], bA[3], kd); FMA2(sB[j], bB[3], kd);
            }
        }

        // |score|*scale + mask; quad-reduce max; exp; quad-reduce sum
        float sAs[16], sBs[16];
        float lmA = -1e30f, lmB = -1e30f;
#pragma unroll
        for (int j = 0; j < 16; j++) {
            float re, im;
            float mb = Mb[l4 + j*4];
            up2(sA[j], re, im);
            sAs[j] = sqrtf(re*re + im*im) * 0.125f + mb;
            up2(sB[j], re, im);
            sBs[j] = sqrtf(re*re + im*im) * 0.125f + mb;
            lmA = fmaxf(lmA, sAs[j]);
            lmB = fmaxf(lmB, sBs[j]);
        }
        lmA = fmaxf(lmA, __shfl_xor_sync(0xffffffffu, lmA, 1));
        lmA = fmaxf(lmA, __shfl_xor_sync(0xffffffffu, lmA, 2));
        lmB = fmaxf(lmB, __shfl_xor_sync(0xffffffffu, lmB, 1));
        lmB = fmaxf(lmB, __shfl_xor_sync(0xffffffffu, lmB, 2));
        float mnewA = fmaxf(mrunA, lmA);
        float mnewB = fmaxf(mrunB, lmB);
        bool vA = (mnewA > -1e29f), vB = (mnewB > -1e29f);
        float sclA = vA ? __expf(mrunA - mnewA) : 1.0f;
        float sclB = vB ? __expf(mrunB - mnewB) : 1.0f;

        float psA = 0.f, psB = 0.f;
#pragma unroll
        for (int j = 0; j < 16; j++) {
            float pA = vA ? __expf(sAs[j] - mnewA) : 0.f;
            float pB = vB ? __expf(sBs[j] - mnewB) : 0.f;
            psA += pA; psB += pB;
            P[qa*SS + l4 + j*4] = pA;
            P[qb*SS + l4 + j*4] = pB;
        }
        psA += __shfl_xor_sync(0xffffffffu, psA, 1);
        psA += __shfl_xor_sync(0xffffffffu, psA, 2);
        psB += __shfl_xor_sync(0xffffffffu, psB, 1);
        psB += __shfl_xor_sync(0xffffffffu, psB, 2);
        lrunA = lrunA * sclA + psA;
        lrunB = lrunB * sclB + psB;
        mrunA = mnewA; mrunB = mnewB;

        {
            u64 sAd = dup2(sclA), sBd = dup2(sclB);
#pragma unroll
            for (int i = 0; i < 8; i++) {
                MUL2(arA[i], arA[i], sAd); MUL2(aiA[i], aiA[i], sAd);
                MUL2(arB[i], arB[i], sBd); MUL2(aiB[i], aiB[i], sBd);
            }
        }
        __syncwarp();   // P rows are quad-private (same warp)

        // ---- AV: packed pairs; V float4s reinterpreted as two f32x2 operands
#pragma unroll 4
        for (int k = 0; k < 64; k++) {
            u64 pAd = dup2(P[qa*SS + k]);
            u64 pBd = dup2(P[qb*SS + k]);
#pragma unroll
            for (int j = 0; j < 4; j++) {
                ulonglong2 v = *(ulonglong2*)(Vr + k*SS + l4*4 + j*16);
                FMA2(arA[2*j  ], pAd, v.x); FMA2(arA[2*j+1], pAd, v.y);
                FMA2(arB[2*j  ], pBd, v.x); FMA2(arB[2*j+1], pBd, v.y);
                ulonglong2 w = *(ulonglong2*)(Vi + k*SS + l4*4 + j*16);
                FMA2(aiA[2*j  ], pAd, w.x); FMA2(aiA[2*j+1], pAd, w.y);
                FMA2(aiB[2*j  ], pBd, w.x); FMA2(aiB[2*j+1], pBd, w.y);
            }
        }
    }

    // epilogue
    float invA = (lrunA > 0.f) ? (1.0f / lrunA) : 0.0f;
    float invB = (lrunB > 0.f) ? (1.0f / lrunB) : 0.0f;
    float* outrA = g_Ar + (size_t)(b*NQ + q0 + qa) * OPROJ + h*DHEAD + l4*4;
    float* outiA = g_Ai + (size_t)(b*NQ + q0 + qa) * OPROJ + h*DHEAD + l4*4;
    float* outrB = g_Ar + (size_t)(b*NQ + q0 + qb) * OPROJ + h*DHEAD + l4*4;
    float* outiB = g_Ai + (size_t)(b*NQ + q0 + qb) * OPROJ + h*DHEAD + l4*4;
#pragma unroll
    for (int j = 0; j < 4; j++) {
        float x0,x1,x2,x3;
        float4 o;
        up2(arA[2*j], x0, x1); up2(arA[2*j+1], x2, x3);
        o.x = x0*invA; o.y = x1*invA; o.z = x2*invA; o.w = x3*invA;
        *(float4*)(outrA + j*16) = o;
        up2(aiA[2*j], x0, x1); up2(aiA[2*j+1], x2, x3);
        o.x = x0*invA; o.y = x1*invA; o.z = x2*invA; o.w = x3*invA;
        *(float4*)(outiA + j*16) = o;
        up2(arB[2*j], x0, x1); up2(arB[2*j+1], x2, x3);
        o.x = x0*invB; o.y = x1*invB; o.z = x2*invB; o.w = x3*invB;
        *(float4*)(outrB + j*16) = o;
        up2(aiB[2*j], x0, x1); up2(aiB[2*j+1], x2, x3);
        o.x = x0*invB; o.y = x1*invB; o.z = x2*invB; o.w = x3*invB;
        *(float4*)(outiB + j*16) = o;
    }
}

// ---------------- launch ----------------
extern "C" void kernel_launch(void* const* d_in, const int* in_sizes, int n_in,
                              void* d_out, int out_size) {
    const float* big[6] = {0,0,0,0,0,0};
    const float* wts[8] = {0,0,0,0,0,0,0,0};
    const void*  maskp  = nullptr;
    int nbig = 0, nw = 0;
    for (int i = 0; i < n_in; i++) {
        int s = in_sizes[i];
        if (s == 1048576 && nbig < 6)    big[nbig++] = (const float*)d_in[i];
        else if (s == 131072 && nw < 8)  wts[nw++]   = (const float*)d_in[i];
        else if (s == 4096 && !maskp)    maskp       = d_in[i];
    }
    if (nbig != 6 || nw != 8) {
        for (int i = 0; i < 6; i++) big[i] = (i < n_in) ? (const float*)d_in[i] : nullptr;
        for (int i = 0; i < 8; i++) wts[i] = (6 + i < n_in) ? (const float*)d_in[6 + i] : nullptr;
        maskp = (n_in >= 15) ? d_in[14] : nullptr;
    }

    const float *Qre = big[0], *Qim = big[1], *Kre = big[2], *Kim = big[3], *Vre = big[4], *Vim = big[5];
    const float *WQr = wts[0], *WQi = wts[1], *WKr = wts[2], *WKi = wts[3];
    const float *WVr = wts[4], *WVi = wts[5], *WOr = wts[6], *WOi = wts[7];

    cudaFuncSetAttribute(attn_kernel, cudaFuncAttributeMaxDynamicSharedMemorySize, ATTN_SMEM);

    mask_kernel<<<1, 256>>>((const unsigned char*)maskp, maskp != nullptr ? 1 : 0);

    dim3 gproj(OPROJ/64, (BB*NQ)/64);
    cgemm_kernel<false><<<gproj, 256>>>(Qre, Qim, WQr, WQi, nullptr, BB*NQ,  OPROJ, RDIM, 0);
    cgemm_kernel<false><<<gproj, 256>>>(Kre, Kim, WKr, WKi, nullptr, BB*NKK, OPROJ, RDIM, 1);
    cgemm_kernel<false><<<gproj, 256>>>(Vre, Vim, WVr, WVi, nullptr, BB*NKK, OPROJ, RDIM, 2);

    dim3 gattn(NQ/128, BH);
    attn_kernel<<<gattn, 256, ATTN_SMEM>>>();

    dim3 gout(RDIM/64, (BB*NQ)/64);
    if (out_size == 2097152)
        cgemm_kernel<false><<<gout, 256>>>(nullptr, nullptr, WOr, WOi, (float*)d_out, BB*NQ, RDIM, OPROJ, 3);
    else
        cgemm_kernel<true ><<<gout, 256>>>(nullptr, nullptr, WOr, WOi, (float*)d_out, BB*NQ, RDIM, OPROJ, 3);
}

// round 15
// speedup vs baseline: 1.6113x; 1.6113x over previous
#include <cuda_runtime.h>
#include <math.h>

// Problem constants
#define BB     4
#define NQ     1024
#define NKK    1024
#define RDIM   256
#define NHH    8
#define DHEAD  64
#define BH     (BB*NHH)      // 32
#define OPROJ  (NHH*DHEAD)   // 512

// ---------------- scratch (static device globals; no allocations) ----------------
__device__ __align__(256) float g_Qpr[BH*NQ*DHEAD];
__device__ __align__(256) float g_Qpi[BH*NQ*DHEAD];
__device__ __align__(256) float g_Kpr[BH*NKK*DHEAD];
__device__ __align__(256) float g_Kpi[BH*NKK*DHEAD];
__device__ __align__(256) float g_Vpr[BH*NKK*DHEAD];
__device__ __align__(256) float g_Vpi[BH*NKK*DHEAD];
__device__ __align__(256) float g_Ar [BB*NQ*OPROJ];
__device__ __align__(256) float g_Ai [BB*NQ*OPROJ];
__device__ __align__(256) float g_maskb[BB*NKK];

// ---- tf32 helpers ----
__device__ __forceinline__ float tf32r(float x) {
    unsigned u; asm("cvt.rna.tf32.f32 %0, %1;" : "=r"(u) : "f"(x));
    return __uint_as_float(u);
}
__device__ __forceinline__ void mma_tf32(float c[4],
    unsigned a0, unsigned a1, unsigned a2, unsigned a3,
    unsigned b0, unsigned b1)
{
    asm("mma.sync.aligned.m16n8k8.row.col.f32.tf32.tf32.f32 "
        "{%0,%1,%2,%3}, {%4,%5,%6,%7}, {%8,%9}, {%0,%1,%2,%3};"
        : "+f"(c[0]), "+f"(c[1]), "+f"(c[2]), "+f"(c[3])
        : "r"(a0), "r"(a1), "r"(a2), "r"(a3), "r"(b0), "r"(b1));
}

// ---------------- mask sniff + convert (uint8 / int32 / f32 / bf16) ----------------
__global__ void mask_kernel(const unsigned char* __restrict__ mp, int present) {
    __shared__ int s_flags;
    if (threadIdx.x == 0) s_flags = 0;
    __syncthreads();
    if (!present) {
        for (int k = threadIdx.x; k < BB*NKK; k += blockDim.x) g_maskb[k] = 0.0f;
        return;
    }
    int f = 0;
    for (int i = threadIdx.x; i < BB*NKK; i += blockDim.x) {
        unsigned char v = mp[i];
        if (v) {
            int p = i & 3;
            if (v == 0x3F)      { if (p == 1) f |= 2;  else if (p == 3) f |= 4;  else f |= 1; }
            else if (v == 0x80) { if (p == 0) f |= 8;  else if (p == 2) f |= 16; else f |= 1; }
            else                { if (p != 0) f |= 1;  else f |= 32; }
        }
    }
    if (f) atomicOr(&s_flags, f);
    __syncthreads();
    int F = s_flags;
    int mode;
    if      (F & (2|8))  mode = 3;
    else if (F & (4|16)) mode = 2;
    else if (F & 1)      mode = 0;
    else if (F & 32)     mode = 1;
    else                 mode = 0;

    for (int k = threadIdx.x; k < BB*NKK; k += blockDim.x) {
        bool m;
        if      (mode == 0) m = mp[k] != 0;
        else if (mode == 1) m = ((const int*)mp)[k] != 0;
        else if (mode == 2) m = ((const float*)mp)[k] != 0.0f;
        else                m = ((const unsigned short*)mp)[k] != 0;
        g_maskb[k] = m ? 0.0f : -1e30f;
    }
}

// ---------------- complex GEMM (R13 proven version): double-buffered, transposed tiles ----------------
#define TP 68
template<bool REAL_ONLY>
__global__ __launch_bounds__(256) void cgemm_kernel(
    const float* __restrict__ Xr, const float* __restrict__ Xi,
    const float* __restrict__ Wr, const float* __restrict__ Wi,
    float* __restrict__ Oc, int M, int N, int K, int which)
{
    __shared__ float Xs_r[2][16][TP], Xs_i[2][16][TP];
    __shared__ float Ws_r[2][16][TP], Ws_i[2][16][TP];

    float* Or = nullptr; float* Oi = nullptr;
    if (which == 0)      { Or = g_Qpr; Oi = g_Qpi; }
    else if (which == 1) { Or = g_Kpr; Oi = g_Kpi; }
    else if (which == 2) { Or = g_Vpr; Oi = g_Vpi; }
    else                 { Xr = g_Ar;  Xi = g_Ai;  }

    int tid = threadIdx.x;
    int tx = tid & 15, ty = tid >> 4;
    int m0 = blockIdx.y * 64, n0 = blockIdx.x * 64;
    int lrow = tid >> 2, lc = (tid & 3) * 4;

    float cre[4][4], cim[4][4];
#pragma unroll
    for (int i = 0; i < 4; i++)
#pragma unroll
        for (int j = 0; j < 4; j++) { cre[i][j] = 0.f; if (!REAL_ONLY) cim[i][j] = 0.f; }

    const float* xr_p = Xr + (size_t)(m0 + lrow) * K + lc;
    const float* xi_p = Xi + (size_t)(m0 + lrow) * K + lc;
    const float* wr_p = Wr + (size_t)(n0 + lrow) * K + lc;
    const float* wi_p = Wi + (size_t)(n0 + lrow) * K + lc;

    int NK = K >> 4;

    float4 xr = *(const float4*)(xr_p);
    float4 xi = *(const float4*)(xi_p);
    float4 wr = *(const float4*)(wr_p);
    float4 wi = *(const float4*)(wi_p);
    {
        float xrv[4] = {xr.x,xr.y,xr.z,xr.w}, xiv[4] = {xi.x,xi.y,xi.z,xi.w};
        float wrv[4] = {wr.x,wr.y,wr.z,wr.w}, wiv[4] = {wi.x,wi.y,wi.z,wi.w};
#pragma unroll
        for (int c = 0; c < 4; c++) {
            Xs_r[0][lc+c][lrow] = xrv[c];
            Xs_i[0][lc+c][lrow] = xiv[c];
            Ws_r[0][lc+c][lrow] = wrv[c];
            Ws_i[0][lc+c][lrow] = wiv[c];
        }
    }
    __syncthreads();

    int pb = 0;
    for (int kt = 0; kt < NK; kt++) {
        if (kt + 1 < NK) {
            int k0 = (kt + 1) << 4;
            xr = *(const float4*)(xr_p + k0);
            xi = *(const float4*)(xi_p + k0);
            wr = *(const float4*)(wr_p + k0);
            wi = *(const float4*)(wi_p + k0);
        }
#pragma unroll
        for (int kk = 0; kk < 16; kk++) {
            float4 a_r = *(const float4*)&Xs_r[pb][kk][ty*4];
            float4 a_i = *(const float4*)&Xs_i[pb][kk][ty*4];
            float4 b_r = *(const float4*)&Ws_r[pb][kk][tx*4];
            float4 b_i = *(const float4*)&Ws_i[pb][kk][tx*4];
            float ar[4] = {a_r.x,a_r.y,a_r.z,a_r.w}, ai[4] = {a_i.x,a_i.y,a_i.z,a_i.w};
            float br[4] = {b_r.x,b_r.y,b_r.z,b_r.w}, bi[4] = {b_i.x,b_i.y,b_i.z,b_i.w};
#pragma unroll
            for (int i = 0; i < 4; i++)
#pragma unroll
                for (int j = 0; j < 4; j++) {
                    cre[i][j] += ar[i]*br[j];
                    cre[i][j] -= ai[i]*bi[j];
                    if (!REAL_ONLY) {
                        cim[i][j] += ar[i]*bi[j];
                        cim[i][j] += ai[i]*br[j];
                    }
                }
        }
        __syncthreads();
        if (kt + 1 < NK) {
            float xrv[4] = {xr.x,xr.y,xr.z,xr.w}, xiv[4] = {xi.x,xi.y,xi.z,xi.w};
            float wrv[4] = {wr.x,wr.y,wr.z,wr.w}, wiv[4] = {wi.x,wi.y,wi.z,wi.w};
            int nb = pb ^ 1;
#pragma unroll
            for (int c = 0; c < 4; c++) {
                Xs_r[nb][lc+c][lrow] = xrv[c];
                Xs_i[nb][lc+c][lrow] = xiv[c];
                Ws_r[nb][lc+c][lrow] = wrv[c];
                Ws_i[nb][lc+c][lrow] = wiv[c];
            }
            __syncthreads();
        }
        pb ^= 1;
    }

#pragma unroll
    for (int i = 0; i < 4; i++) {
        int m = m0 + ty*4 + i;
#pragma unroll
        for (int j = 0; j < 4; j++) {
            int o = n0 + tx*4 + j;
            if (which != 3) {
                int b = m >> 10, n = m & 1023;
                int h = o >> 6,  d = o & 63;
                size_t idx = ((size_t)(b*NHH + h) * NQ + n) * 64 + d;
                Or[idx] = cre[i][j];
                Oi[idx] = cim[i][j];
            } else if (REAL_ONLY) {
                Oc[(size_t)m * N + o] = cre[i][j];
            } else {
                size_t base = ((size_t)m * N + o) * 2;
                Oc[base] = cre[i][j]; Oc[base+1] = cim[i][j];
            }
        }
    }
}

// ---------------- fused attention v4: tf32 mma.sync scores + R13 softmax/AV ----------------
// Smem: Qr,Qi: 128xSS (tf32-rounded) | Kr,Ki: 64xSS (tf32-rounded) | Vr,Vi: 64xSS (fp32)
//       P: 128xSS (scores -> probs) | Mb: 64
#define SS 68
#define ATTN_SMEM ((640*SS + 64) * 4)   // 174,336 B

__global__ __launch_bounds__(256, 1) void attn_kernel() {
    extern __shared__ float sm[];
    float* Qr = sm;
    float* Qi = Qr + 128*SS;
    float* Kr = Qi + 128*SS;
    float* Ki = Kr + 64*SS;
    float* Vr = Ki + 64*SS;
    float* Vi = Vr + 64*SS;
    float* P  = Vi + 64*SS;
    float* Mb = P  + 128*SS;

    int tid = threadIdx.x;
    int bh  = blockIdx.y;
    int b   = bh >> 3;
    int h   = bh & 7;
    int q0  = blockIdx.x * 128;

    int warp = tid >> 5, lane = tid & 31;
    int gid  = lane >> 2, tig = lane & 3;   // mma groupID / threadID-in-group
    int m0w  = warp * 16;                   // q-row base of this warp's mma tiles

    int qa = tid >> 2;        // softmax/AV: local q row A (0..63)
    int qb = qa + 64;         // local q row B
    int l4 = tid & 3;         // quad lane

    // load Q tile (128 q x 64 d, re/im), rounded to tf32
    const float* Qpr = g_Qpr + ((size_t)bh * NQ + q0) * 64;
    const float* Qpi = g_Qpi + ((size_t)bh * NQ + q0) * 64;
    for (int t = tid; t < 128*16; t += 256) {
        int r = t >> 4, c = (t & 15) * 4;
        float4 v = *(const float4*)(Qpr + r*64 + c);
        v.x = tf32r(v.x); v.y = tf32r(v.y); v.z = tf32r(v.z); v.w = tf32r(v.w);
        *(float4*)(Qr + r*SS + c) = v;
        v = *(const float4*)(Qpi + r*64 + c);
        v.x = tf32r(v.x); v.y = tf32r(v.y); v.z = tf32r(v.z); v.w = tf32r(v.w);
        *(float4*)(Qi + r*SS + c) = v;
    }

    const float* Kbr = g_Kpr + (size_t)bh * NKK * 64;
    const float* Kbi = g_Kpi + (size_t)bh * NKK * 64;
    const float* Vbr = g_Vpr + (size_t)bh * NKK * 64;
    const float* Vbi = g_Vpi + (size_t)bh * NKK * 64;

    float mrunA = -1e30f, lrunA = 0.f;
    float mrunB = -1e30f, lrunB = 0.f;
    float4 accrA[4], acciA[4], accrB[4], acciB[4];
#pragma unroll
    for (int j = 0; j < 4; j++) {
        accrA[j] = make_float4(0.f,0.f,0.f,0.f); acciA[j] = make_float4(0.f,0.f,0.f,0.f);
        accrB[j] = make_float4(0.f,0.f,0.f,0.f); acciB[j] = make_float4(0.f,0.f,0.f,0.f);
    }

    for (int kt = 0; kt < NKK/64; kt++) {
        int k0 = kt * 64;
        __syncthreads();
        for (int t = tid; t < 64*16; t += 256) {
            int r = t >> 4, c = (t & 15) * 4;
            float4 v = *(const float4*)(Kbr + (size_t)(k0+r)*64 + c);
            v.x = tf32r(v.x); v.y = tf32r(v.y); v.z = tf32r(v.z); v.w = tf32r(v.w);
            *(float4*)(Kr + r*SS + c) = v;
            v = *(const float4*)(Kbi + (size_t)(k0+r)*64 + c);
            v.x = tf32r(v.x); v.y = tf32r(v.y); v.z = tf32r(v.z); v.w = tf32r(v.w);
            *(float4*)(Ki + r*SS + c) = v;
            *(float4*)(Vr + r*SS + c) = *(const float4*)(Vbr + (size_t)(k0+r)*64 + c);
            *(float4*)(Vi + r*SS + c) = *(const float4*)(Vbi + (size_t)(k0+r)*64 + c);
        }
        if (tid < 64) Mb[tid] = g_maskb[b*NKK + k0 + tid];
        __syncthreads();

        // ---- scores via tf32 mma: warp owns 16 q rows x 64 k
        float accRe[8][4], accIm[8][4];
#pragma unroll
        for (int n = 0; n < 8; n++)
#pragma unroll
            for (int c = 0; c < 4; c++) { accRe[n][c] = 0.f; accIm[n][c] = 0.f; }

#pragma unroll
        for (int d = 0; d < 64; d += 8) {
            const float* qrp = Qr + (m0w + gid)*SS + d + tig;
            const float* qip = Qi + (m0w + gid)*SS + d + tig;
            unsigned ar0 = __float_as_uint(qrp[0]);
            unsigned ar1 = __float_as_uint(qrp[8*SS]);
            unsigned ar2 = __float_as_uint(qrp[4]);
            unsigned ar3 = __float_as_uint(qrp[8*SS + 4]);
            unsigned ai0 = __float_as_uint(qip[0]);
            unsigned ai1 = __float_as_uint(qip[8*SS]);
            unsigned ai2 = __float_as_uint(qip[4]);
            unsigned ai3 = __float_as_uint(qip[8*SS + 4]);
#pragma unroll
            for (int n = 0; n < 8; n++) {
                int kk = n*8 + gid;
                const float* krp = Kr + kk*SS + d + tig;
                const float* kip = Ki + kk*SS + d + tig;
                unsigned br0 = __float_as_uint(krp[0]);
                unsigned br1 = __float_as_uint(krp[4]);
                float bi0f = kip[0], bi1f = kip[4];
                unsigned bi0  = __float_as_uint(bi0f);
                unsigned bi1  = __float_as_uint(bi1f);
                unsigned nbi0 = __float_as_uint(-bi0f);
                unsigned nbi1 = __float_as_uint(-bi1f);
                mma_tf32(accRe[n], ar0,ar1,ar2,ar3, br0,br1);   // Qr.Kr
                mma_tf32(accRe[n], ai0,ai1,ai2,ai3, bi0,bi1);   // + Qi.Ki
                mma_tf32(accIm[n], ai0,ai1,ai2,ai3, br0,br1);   // Qi.Kr
                mma_tf32(accIm[n], ar0,ar1,ar2,ar3, nbi0,nbi1); // - Qr.Ki
            }
        }

        // |s|*scale + mask -> P.  C layout: c0:(gid, 2t) c1:(gid, 2t+1) c2:(gid+8, 2t) c3:(gid+8, 2t+1)
        {
            int r0 = m0w + gid, r1 = r0 + 8;
#pragma unroll
            for (int n = 0; n < 8; n++) {
                int kc = n*8 + tig*2;
                float mb0 = Mb[kc], mb1 = Mb[kc+1];
                P[r0*SS + kc  ] = sqrtf(accRe[n][0]*accRe[n][0] + accIm[n][0]*accIm[n][0]) * 0.125f + mb0;
                P[r0*SS + kc+1] = sqrtf(accRe[n][1]*accRe[n][1] + accIm[n][1]*accIm[n][1]) * 0.125f + mb1;
                P[r1*SS + kc  ] = sqrtf(accRe[n][2]*accRe[n][2] + accIm[n][2]*accIm[n][2]) * 0.125f + mb0;
                P[r1*SS + kc+1] = sqrtf(accRe[n][3]*accRe[n][3] + accIm[n][3]*accIm[n][3]) * 0.125f + mb1;
            }
        }
        __syncthreads();

        // ---- online softmax on P rows (quad-based, as R13)
        float sAs[16], sBs[16];
        float lmA = -1e30f, lmB = -1e30f;
#pragma unroll
        for (int j = 0; j < 16; j++) {
            sAs[j] = P[qa*SS + l4 + j*4];
            sBs[j] = P[qb*SS + l4 + j*4];
            lmA = fmaxf(lmA, sAs[j]);
            lmB = fmaxf(lmB, sBs[j]);
        }
        lmA = fmaxf(lmA, __shfl_xor_sync(0xffffffffu, lmA, 1));
        lmA = fmaxf(lmA, __shfl_xor_sync(0xffffffffu, lmA, 2));
        lmB = fmaxf(lmB, __shfl_xor_sync(0xffffffffu, lmB, 1));
        lmB = fmaxf(lmB, __shfl_xor_sync(0xffffffffu, lmB, 2));
        float mnewA = fmaxf(mrunA, lmA);
        float mnewB = fmaxf(mrunB, lmB);
        bool vA = (mnewA > -1e29f), vB = (mnewB > -1e29f);
        float sclA = vA ? __expf(mrunA - mnewA) : 1.0f;
        float sclB = vB ? __expf(mrunB - mnewB) : 1.0f;

        float psA = 0.f, psB = 0.f;
#pragma unroll
        for (int j = 0; j < 16; j++) {
            float pA = vA ? __expf(sAs[j] - mnewA) : 0.f;
            float pB = vB ? __expf(sBs[j] - mnewB) : 0.f;
            psA += pA; psB += pB;
            P[qa*SS + l4 + j*4] = pA;
            P[qb*SS + l4 + j*4] = pB;
        }
        psA += __shfl_xor_sync(0xffffffffu, psA, 1);
        psA += __shfl_xor_sync(0xffffffffu, psA, 2);
        psB += __shfl_xor_sync(0xffffffffu, psB, 1);
        psB += __shfl_xor_sync(0xffffffffu, psB, 2);
        lrunA = lrunA * sclA + psA;
        lrunB = lrunB * sclB + psB;
        mrunA = mnewA; mrunB = mnewB;

#pragma unroll
        for (int j = 0; j < 4; j++) {
            accrA[j].x *= sclA; accrA[j].y *= sclA; accrA[j].z *= sclA; accrA[j].w *= sclA;
            acciA[j].x *= sclA; acciA[j].y *= sclA; acciA[j].z *= sclA; acciA[j].w *= sclA;
            accrB[j].x *= sclB; accrB[j].y *= sclB; accrB[j].z *= sclB; accrB[j].w *= sclB;
            acciB[j].x *= sclB; acciB[j].y *= sclB; acciB[j].z *= sclB; acciB[j].w *= sclB;
        }
        __syncwarp();   // P rows quad-private between exp-write and AV-read

        // ---- AV (R13 form)
#pragma unroll 4
        for (int k = 0; k < 64; k++) {
            float pA = P[qa*SS + k];
            float pB = P[qb*SS + k];
#pragma unroll
            for (int j = 0; j < 4; j++) {
                float4 v = *(float4*)(Vr + k*SS + l4*4 + j*16);
                accrA[j].x += pA*v.x; accrA[j].y += pA*v.y; accrA[j].z += pA*v.z; accrA[j].w += pA*v.w;
                accrB[j].x += pB*v.x; accrB[j].y += pB*v.y; accrB[j].z += pB*v.z; accrB[j].w += pB*v.w;
                float4 w = *(float4*)(Vi + k*SS + l4*4 + j*16);
                acciA[j].x += pA*w.x; acciA[j].y += pA*w.y; acciA[j].z += pA*w.z; acciA[j].w += pA*w.w;
                acciB[j].x += pB*w.x; acciB[j].y += pB*w.y; acciB[j].z += pB*w.z; acciB[j].w += pB*w.w;
            }
        }
    }

    // epilogue
    float invA = (lrunA > 0.f) ? (1.0f / lrunA) : 0.0f;
    float invB = (lrunB > 0.f) ? (1.0f / lrunB) : 0.0f;
    float* outrA = g_Ar + (size_t)(b*NQ + q0 + qa) * OPROJ + h*DHEAD + l4*4;
    float* outiA = g_Ai + (size_t)(b*NQ + q0 + qa) * OPROJ + h*DHEAD + l4*4;
    float* outrB = g_Ar + (size_t)(b*NQ + q0 + qb) * OPROJ + h*DHEAD + l4*4;
    float* outiB = g_Ai + (size_t)(b*NQ + q0 + qb) * OPROJ + h*DHEAD + l4*4;
#pragma unroll
    for (int j = 0; j < 4; j++) {
        float4 o;
        o.x = accrA[j].x*invA; o.y = accrA[j].y*invA; o.z = accrA[j].z*invA; o.w = accrA[j].w*invA;
        *(float4*)(outrA + j*16) = o;
        o.x = acciA[j].x*invA; o.y = acciA[j].y*invA; o.z = acciA[j].z*invA; o.w = acciA[j].w*invA;
        *(float4*)(outiA + j*16) = o;
        o.x = accrB[j].x*invB; o.y = accrB[j].y*invB; o.z = accrB[j].z*invB; o.w = accrB[j].w*invB;
        *(float4*)(outrB + j*16) = o;
        o.x = acciB[j].x*invB; o.y = acciB[j].y*invB; o.z = acciB[j].z*invB; o.w = acciB[j].w*invB;
        *(float4*)(outiB + j*16) = o;
    }
}

// ---------------- launch ----------------
extern "C" void kernel_launch(void* const* d_in, const int* in_sizes, int n_in,
                              void* d_out, int out_size) {
    const float* big[6] = {0,0,0,0,0,0};
    const float* wts[8] = {0,0,0,0,0,0,0,0};
    const void*  maskp  = nullptr;
    int nbig = 0, nw = 0;
    for (int i = 0; i < n_in; i++) {
        int s = in_sizes[i];
        if (s == 1048576 && nbig < 6)    big[nbig++] = (const float*)d_in[i];
        else if (s == 131072 && nw < 8)  wts[nw++]   = (const float*)d_in[i];
        else if (s == 4096 && !maskp)    maskp       = d_in[i];
    }
    if (nbig != 6 || nw != 8) {
        for (int i = 0; i < 6; i++) big[i] = (i < n_in) ? (const float*)d_in[i] : nullptr;
        for (int i = 0; i < 8; i++) wts[i] = (6 + i < n_in) ? (const float*)d_in[6 + i] : nullptr;
        maskp = (n_in >= 15) ? d_in[14] : nullptr;
    }

    const float *Qre = big[0], *Qim = big[1], *Kre = big[2], *Kim = big[3], *Vre = big[4], *Vim = big[5];
    const float *WQr = wts[0], *WQi = wts[1], *WKr = wts[2], *WKi = wts[3];
    const float *WVr = wts[4], *WVi = wts[5], *WOr = wts[6], *WOi = wts[7];

    cudaFuncSetAttribute(attn_kernel, cudaFuncAttributeMaxDynamicSharedMemorySize, ATTN_SMEM);

    mask_kernel<<<1, 256>>>((const unsigned char*)maskp, maskp != nullptr ? 1 : 0);

    dim3 gproj(OPROJ/64, (BB*NQ)/64);
    cgemm_kernel<false><<<gproj, 256>>>(Qre, Qim, WQr, WQi, nullptr, BB*NQ,  OPROJ, RDIM, 0);
    cgemm_kernel<false><<<gproj, 256>>>(Kre, Kim, WKr, WKi, nullptr, BB*NKK, OPROJ, RDIM, 1);
    cgemm_kernel<false><<<gproj, 256>>>(Vre, Vim, WVr, WVi, nullptr, BB*NKK, OPROJ, RDIM, 2);

    dim3 gattn(NQ/128, BH);
    attn_kernel<<<gattn, 256, ATTN_SMEM>>>();

    dim3 gout(RDIM/64, (BB*NQ)/64);
    if (out_size == 2097152)
        cgemm_kernel<false><<<gout, 256>>>(nullptr, nullptr, WOr, WOi, (float*)d_out, BB*NQ, RDIM, OPROJ, 3);
    else
        cgemm_kernel<true ><<<gout, 256>>>(nullptr, nullptr, WOr, WOi, (float*)d_out, BB*NQ, RDIM, OPROJ, 3);
}

// round 16
// speedup vs baseline: 2.0476x; 1.2707x over previous
#include <cuda_runtime.h>
#include <math.h>

// Problem constants
#define BB     4
#define NQ     1024
#define NKK    1024
#define RDIM   256
#define NHH    8
#define DHEAD  64
#define BH     (BB*NHH)      // 32
#define OPROJ  (NHH*DHEAD)   // 512

// ---------------- scratch (static device globals; no allocations) ----------------
__device__ __align__(256) float g_Qpr[BH*NQ*DHEAD];
__device__ __align__(256) float g_Qpi[BH*NQ*DHEAD];
__device__ __align__(256) float g_Kpr[BH*NKK*DHEAD];
__device__ __align__(256) float g_Kpi[BH*NKK*DHEAD];
__device__ __align__(256) float g_Vpr[BH*NKK*DHEAD];
__device__ __align__(256) float g_Vpi[BH*NKK*DHEAD];
__device__ __align__(256) float g_Ar [BB*NQ*OPROJ];
__device__ __align__(256) float g_Ai [BB*NQ*OPROJ];
__device__ __align__(256) float g_maskb[BB*NKK];

// ---- tf32 helpers ----
__device__ __forceinline__ float tf32r(float x) {
    unsigned u; asm("cvt.rna.tf32.f32 %0, %1;" : "=r"(u) : "f"(x));
    return __uint_as_float(u);
}
__device__ __forceinline__ void mma_tf32(float c[4],
    unsigned a0, unsigned a1, unsigned a2, unsigned a3,
    unsigned b0, unsigned b1)
{
    asm("mma.sync.aligned.m16n8k8.row.col.f32.tf32.tf32.f32 "
        "{%0,%1,%2,%3}, {%4,%5,%6,%7}, {%8,%9}, {%0,%1,%2,%3};"
        : "+f"(c[0]), "+f"(c[1]), "+f"(c[2]), "+f"(c[3])
        : "r"(a0), "r"(a1), "r"(a2), "r"(a3), "r"(b0), "r"(b1));
}

// ---------------- mask sniff + convert (uint8 / int32 / f32 / bf16) ----------------
__global__ void mask_kernel(const unsigned char* __restrict__ mp, int present) {
    __shared__ int s_flags;
    if (threadIdx.x == 0) s_flags = 0;
    __syncthreads();
    if (!present) {
        for (int k = threadIdx.x; k < BB*NKK; k += blockDim.x) g_maskb[k] = 0.0f;
        return;
    }
    int f = 0;
    for (int i = threadIdx.x; i < BB*NKK; i += blockDim.x) {
        unsigned char v = mp[i];
        if (v) {
            int p = i & 3;
            if (v == 0x3F)      { if (p == 1) f |= 2;  else if (p == 3) f |= 4;  else f |= 1; }
            else if (v == 0x80) { if (p == 0) f |= 8;  else if (p == 2) f |= 16; else f |= 1; }
            else                { if (p != 0) f |= 1;  else f |= 32; }
        }
    }
    if (f) atomicOr(&s_flags, f);
    __syncthreads();
    int F = s_flags;
    int mode;
    if      (F & (2|8))  mode = 3;
    else if (F & (4|16)) mode = 2;
    else if (F & 1)      mode = 0;
    else if (F & 32)     mode = 1;
    else                 mode = 0;

    for (int k = threadIdx.x; k < BB*NKK; k += blockDim.x) {
        bool m;
        if      (mode == 0) m = mp[k] != 0;
        else if (mode == 1) m = ((const int*)mp)[k] != 0;
        else if (mode == 2) m = ((const float*)mp)[k] != 0.0f;
        else                m = ((const unsigned short*)mp)[k] != 0;
        g_maskb[k] = m ? 0.0f : -1e30f;
    }
}

// ---------------- complex GEMM v4: tf32 mma.sync, double-buffered row-major tiles ----------------
// out = X @ W^T, X:(M,K) W:(N,K), complex.
// 64x64 block tile; 8 warps = 4 m-tiles(16) x 2 n-halves(32); warp does 4 n-tiles of m16n8k8.
// which: 0->Qp, 1->Kp, 2->Vp (planar head-major); 3->final projection.
#define TW 20   // smem row stride (16 k + 4 pad)
template<bool REAL_ONLY>
__global__ __launch_bounds__(256) void cgemm_kernel(
    const float* __restrict__ Xr, const float* __restrict__ Xi,
    const float* __restrict__ Wr, const float* __restrict__ Wi,
    float* __restrict__ Oc, int M, int N, int K, int which)
{
    __shared__ float Xs_r[2][64][TW], Xs_i[2][64][TW];
    __shared__ float Ws_r[2][64][TW], Ws_i[2][64][TW];

    float* Or = nullptr; float* Oi = nullptr;
    if (which == 0)      { Or = g_Qpr; Oi = g_Qpi; }
    else if (which == 1) { Or = g_Kpr; Oi = g_Kpi; }
    else if (which == 2) { Or = g_Vpr; Oi = g_Vpi; }
    else                 { Xr = g_Ar;  Xi = g_Ai;  }

    int tid = threadIdx.x;
    int m0 = blockIdx.y * 64, n0 = blockIdx.x * 64;
    int lrow = tid >> 2, lc = (tid & 3) * 4;

    int warp = tid >> 5, lane = tid & 31;
    int gid = lane >> 2, tig = lane & 3;
    int m0w = (warp >> 1) * 16;     // warp's m-tile base (0,16,32,48)
    int n0w = (warp & 1) * 32;      // warp's n-half base (0,32)

    // accumulators: 4 n-tiles x c[4]
    float accRe[4][4], accIm[4][4];
#pragma unroll
    for (int t = 0; t < 4; t++)
#pragma unroll
        for (int c = 0; c < 4; c++) { accRe[t][c] = 0.f; if (!REAL_ONLY) accIm[t][c] = 0.f; }

    const float* xr_p = Xr + (size_t)(m0 + lrow) * K + lc;
    const float* xi_p = Xi + (size_t)(m0 + lrow) * K + lc;
    const float* wr_p = Wr + (size_t)(n0 + lrow) * K + lc;
    const float* wi_p = Wi + (size_t)(n0 + lrow) * K + lc;

    int NK = K >> 4;

    // preload chunk 0 (rounded to tf32 at STS)
    float4 xr = *(const float4*)(xr_p);
    float4 xi = *(const float4*)(xi_p);
    float4 wr = *(const float4*)(wr_p);
    float4 wi = *(const float4*)(wi_p);
    {
        Xs_r[0][lrow][lc  ] = tf32r(xr.x); Xs_r[0][lrow][lc+1] = tf32r(xr.y);
        Xs_r[0][lrow][lc+2] = tf32r(xr.z); Xs_r[0][lrow][lc+3] = tf32r(xr.w);
        Xs_i[0][lrow][lc  ] = tf32r(xi.x); Xs_i[0][lrow][lc+1] = tf32r(xi.y);
        Xs_i[0][lrow][lc+2] = tf32r(xi.z); Xs_i[0][lrow][lc+3] = tf32r(xi.w);
        Ws_r[0][lrow][lc  ] = tf32r(wr.x); Ws_r[0][lrow][lc+1] = tf32r(wr.y);
        Ws_r[0][lrow][lc+2] = tf32r(wr.z); Ws_r[0][lrow][lc+3] = tf32r(wr.w);
        Ws_i[0][lrow][lc  ] = tf32r(wi.x); Ws_i[0][lrow][lc+1] = tf32r(wi.y);
        Ws_i[0][lrow][lc+2] = tf32r(wi.z); Ws_i[0][lrow][lc+3] = tf32r(wi.w);
    }
    __syncthreads();

    int pb = 0;
    for (int kt = 0; kt < NK; kt++) {
        if (kt + 1 < NK) {
            int k0 = (kt + 1) << 4;
            xr = *(const float4*)(xr_p + k0);
            xi = *(const float4*)(xi_p + k0);
            wr = *(const float4*)(wr_p + k0);
            wi = *(const float4*)(wi_p + k0);
        }
        // 2 k-steps of 8
#pragma unroll
        for (int ks = 0; ks < 16; ks += 8) {
            unsigned ar0 = __float_as_uint(Xs_r[pb][m0w+gid  ][ks+tig  ]);
            unsigned ar1 = __float_as_uint(Xs_r[pb][m0w+gid+8][ks+tig  ]);
            unsigned ar2 = __float_as_uint(Xs_r[pb][m0w+gid  ][ks+tig+4]);
            unsigned ar3 = __float_as_uint(Xs_r[pb][m0w+gid+8][ks+tig+4]);
            unsigned ai0 = __float_as_uint(Xs_i[pb][m0w+gid  ][ks+tig  ]);
            unsigned ai1 = __float_as_uint(Xs_i[pb][m0w+gid+8][ks+tig  ]);
            unsigned ai2 = __float_as_uint(Xs_i[pb][m0w+gid  ][ks+tig+4]);
            unsigned ai3 = __float_as_uint(Xs_i[pb][m0w+gid+8][ks+tig+4]);
#pragma unroll
            for (int t = 0; t < 4; t++) {
                int n = n0w + t*8 + gid;
                unsigned br0 = __float_as_uint(Ws_r[pb][n][ks+tig  ]);
                unsigned br1 = __float_as_uint(Ws_r[pb][n][ks+tig+4]);
                float bi0f = Ws_i[pb][n][ks+tig  ];
                float bi1f = Ws_i[pb][n][ks+tig+4];
                unsigned nbi0 = __float_as_uint(-bi0f);
                unsigned nbi1 = __float_as_uint(-bi1f);
                mma_tf32(accRe[t], ar0,ar1,ar2,ar3, br0,br1);    // Xr.Wr
                mma_tf32(accRe[t], ai0,ai1,ai2,ai3, nbi0,nbi1);  // - Xi.Wi
                if (!REAL_ONLY) {
                    unsigned bi0 = __float_as_uint(bi0f);
                    unsigned bi1 = __float_as_uint(bi1f);
                    mma_tf32(accIm[t], ar0,ar1,ar2,ar3, bi0,bi1);   // Xr.Wi
                    mma_tf32(accIm[t], ai0,ai1,ai2,ai3, br0,br1);   // + Xi.Wr
                }
            }
        }
        __syncthreads();
        if (kt + 1 < NK) {
            int nb = pb ^ 1;
            Xs_r[nb][lrow][lc  ] = tf32r(xr.x); Xs_r[nb][lrow][lc+1] = tf32r(xr.y);
            Xs_r[nb][lrow][lc+2] = tf32r(xr.z); Xs_r[nb][lrow][lc+3] = tf32r(xr.w);
            Xs_i[nb][lrow][lc  ] = tf32r(xi.x); Xs_i[nb][lrow][lc+1] = tf32r(xi.y);
            Xs_i[nb][lrow][lc+2] = tf32r(xi.z); Xs_i[nb][lrow][lc+3] = tf32r(xi.w);
            Ws_r[nb][lrow][lc  ] = tf32r(wr.x); Ws_r[nb][lrow][lc+1] = tf32r(wr.y);
            Ws_r[nb][lrow][lc+2] = tf32r(wr.z); Ws_r[nb][lrow][lc+3] = tf32r(wr.w);
            Ws_i[nb][lrow][lc  ] = tf32r(wi.x); Ws_i[nb][lrow][lc+1] = tf32r(wi.y);
            Ws_i[nb][lrow][lc+2] = tf32r(wi.z); Ws_i[nb][lrow][lc+3] = tf32r(wi.w);
            __syncthreads();
        }
        pb ^= 1;
    }

    // epilogue: C frag layout c0:(gid,2tig) c1:(gid,2tig+1) c2:(gid+8,2tig) c3:(gid+8,2tig+1)
#pragma unroll
    for (int t = 0; t < 4; t++) {
#pragma unroll
        for (int c = 0; c < 4; c++) {
            int mrow = m0 + m0w + gid + ((c & 2) ? 8 : 0);
            int o    = n0 + n0w + t*8 + 2*tig + (c & 1);
            float re = accRe[t][c];
            if (which != 3) {
                float im = accIm[t][c];
                int b = mrow >> 10, n = mrow & 1023;
                int h = o >> 6,  d = o & 63;
                size_t idx = ((size_t)(b*NHH + h) * NQ + n) * 64 + d;
                Or[idx] = re;
                Oi[idx] = im;
            } else if (REAL_ONLY) {
                Oc[(size_t)mrow * N + o] = re;
            } else {
                size_t base = ((size_t)mrow * N + o) * 2;
                Oc[base] = re; Oc[base+1] = accIm[t][c];
            }
        }
    }
}

// ---------------- fused attention v4 (R15, unchanged): tf32 mma scores + quad softmax/AV ----------------
#define SS 68
#define ATTN_SMEM ((640*SS + 64) * 4)   // 174,336 B

__global__ __launch_bounds__(256, 1) void attn_kernel() {
    extern __shared__ float sm[];
    float* Qr = sm;
    float* Qi = Qr + 128*SS;
    float* Kr = Qi + 128*SS;
    float* Ki = Kr + 64*SS;
    float* Vr = Ki + 64*SS;
    float* Vi = Vr + 64*SS;
    float* P  = Vi + 64*SS;
    float* Mb = P  + 128*SS;

    int tid = threadIdx.x;
    int bh  = blockIdx.y;
    int b   = bh >> 3;
    int h   = bh & 7;
    int q0  = blockIdx.x * 128;

    int warp = tid >> 5, lane = tid & 31;
    int gid  = lane >> 2, tig = lane & 3;
    int m0w  = warp * 16;

    int qa = tid >> 2;
    int qb = qa + 64;
    int l4 = tid & 3;

    const float* Qpr = g_Qpr + ((size_t)bh * NQ + q0) * 64;
    const float* Qpi = g_Qpi + ((size_t)bh * NQ + q0) * 64;
    for (int t = tid; t < 128*16; t += 256) {
        int r = t >> 4, c = (t & 15) * 4;
        float4 v = *(const float4*)(Qpr + r*64 + c);
        v.x = tf32r(v.x); v.y = tf32r(v.y); v.z = tf32r(v.z); v.w = tf32r(v.w);
        *(float4*)(Qr + r*SS + c) = v;
        v = *(const float4*)(Qpi + r*64 + c);
        v.x = tf32r(v.x); v.y = tf32r(v.y); v.z = tf32r(v.z); v.w = tf32r(v.w);
        *(float4*)(Qi + r*SS + c) = v;
    }

    const float* Kbr = g_Kpr + (size_t)bh * NKK * 64;
    const float* Kbi = g_Kpi + (size_t)bh * NKK * 64;
    const float* Vbr = g_Vpr + (size_t)bh * NKK * 64;
    const float* Vbi = g_Vpi + (size_t)bh * NKK * 64;

    float mrunA = -1e30f, lrunA = 0.f;
    float mrunB = -1e30f, lrunB = 0.f;
    float4 accrA[4], acciA[4], accrB[4], acciB[4];
#pragma unroll
    for (int j = 0; j < 4; j++) {
        accrA[j] = make_float4(0.f,0.f,0.f,0.f); acciA[j] = make_float4(0.f,0.f,0.f,0.f);
        accrB[j] = make_float4(0.f,0.f,0.f,0.f); acciB[j] = make_float4(0.f,0.f,0.f,0.f);
    }

    for (int kt = 0; kt < NKK/64; kt++) {
        int k0 = kt * 64;
        __syncthreads();
        for (int t = tid; t < 64*16; t += 256) {
            int r = t >> 4, c = (t & 15) * 4;
            float4 v = *(const float4*)(Kbr + (size_t)(k0+r)*64 + c);
            v.x = tf32r(v.x); v.y = tf32r(v.y); v.z = tf32r(v.z); v.w = tf32r(v.w);
            *(float4*)(Kr + r*SS + c) = v;
            v = *(const float4*)(Kbi + (size_t)(k0+r)*64 + c);
            v.x = tf32r(v.x); v.y = tf32r(v.y); v.z = tf32r(v.z); v.w = tf32r(v.w);
            *(float4*)(Ki + r*SS + c) = v;
            *(float4*)(Vr + r*SS + c) = *(const float4*)(Vbr + (size_t)(k0+r)*64 + c);
            *(float4*)(Vi + r*SS + c) = *(const float4*)(Vbi + (size_t)(k0+r)*64 + c);
        }
        if (tid < 64) Mb[tid] = g_maskb[b*NKK + k0 + tid];
        __syncthreads();

        float accRe[8][4], accIm[8][4];
#pragma unroll
        for (int n = 0; n < 8; n++)
#pragma unroll
            for (int c = 0; c < 4; c++) { accRe[n][c] = 0.f; accIm[n][c] = 0.f; }

#pragma unroll
        for (int d = 0; d < 64; d += 8) {
            const float* qrp = Qr + (m0w + gid)*SS + d + tig;
            const float* qip = Qi + (m0w + gid)*SS + d + tig;
            unsigned ar0 = __float_as_uint(qrp[0]);
            unsigned ar1 = __float_as_uint(qrp[8*SS]);
            unsigned ar2 = __float_as_uint(qrp[4]);
            unsigned ar3 = __float_as_uint(qrp[8*SS + 4]);
            unsigned ai0 = __float_as_uint(qip[0]);
            unsigned ai1 = __float_as_uint(qip[8*SS]);
            unsigned ai2 = __float_as_uint(qip[4]);
            unsigned ai3 = __float_as_uint(qip[8*SS + 4]);
#pragma unroll
            for (int n = 0; n < 8; n++) {
                int kk = n*8 + gid;
                const float* krp = Kr + kk*SS + d + tig;
                const float* kip = Ki + kk*SS + d + tig;
                unsigned br0 = __float_as_uint(krp[0]);
                unsigned br1 = __float_as_uint(krp[4]);
                float bi0f = kip[0], bi1f = kip[4];
                unsigned bi0  = __float_as_uint(bi0f);
                unsigned bi1  = __float_as_uint(bi1f);
                unsigned nbi0 = __float_as_uint(-bi0f);
                unsigned nbi1 = __float_as_uint(-bi1f);
                mma_tf32(accRe[n], ar0,ar1,ar2,ar3, br0,br1);
                mma_tf32(accRe[n], ai0,ai1,ai2,ai3, bi0,bi1);
                mma_tf32(accIm[n], ai0,ai1,ai2,ai3, br0,br1);
                mma_tf32(accIm[n], ar0,ar1,ar2,ar3, nbi0,nbi1);
            }
        }

        {
            int r0 = m0w + gid, r1 = r0 + 8;
#pragma unroll
            for (int n = 0; n < 8; n++) {
                int kc = n*8 + tig*2;
                float mb0 = Mb[kc], mb1 = Mb[kc+1];
                P[r0*SS + kc  ] = sqrtf(accRe[n][0]*accRe[n][0] + accIm[n][0]*accIm[n][0]) * 0.125f + mb0;
                P[r0*SS + kc+1] = sqrtf(accRe[n][1]*accRe[n][1] + accIm[n][1]*accIm[n][1]) * 0.125f + mb1;
                P[r1*SS + kc  ] = sqrtf(accRe[n][2]*accRe[n][2] + accIm[n][2]*accIm[n][2]) * 0.125f + mb0;
                P[r1*SS + kc+1] = sqrtf(accRe[n][3]*accRe[n][3] + accIm[n][3]*accIm[n][3]) * 0.125f + mb1;
            }
        }
        __syncthreads();

        float sAs[16], sBs[16];
        float lmA = -1e30f, lmB = -1e30f;
#pragma unroll
        for (int j = 0; j < 16; j++) {
            sAs[j] = P[qa*SS + l4 + j*4];
            sBs[j] = P[qb*SS + l4 + j*4];
            lmA = fmaxf(lmA, sAs[j]);
            lmB = fmaxf(lmB, sBs[j]);
        }
        lmA = fmaxf(lmA, __shfl_xor_sync(0xffffffffu, lmA, 1));
        lmA = fmaxf(lmA, __shfl_xor_sync(0xffffffffu, lmA, 2));
        lmB = fmaxf(lmB, __shfl_xor_sync(0xffffffffu, lmB, 1));
        lmB = fmaxf(lmB, __shfl_xor_sync(0xffffffffu, lmB, 2));
        float mnewA = fmaxf(mrunA, lmA);
        float mnewB = fmaxf(mrunB, lmB);
        bool vA = (mnewA > -1e29f), vB = (mnewB > -1e29f);
        float sclA = vA ? __expf(mrunA - mnewA) : 1.0f;
        float sclB = vB ? __expf(mrunB - mnewB) : 1.0f;

        float psA = 0.f, psB = 0.f;
#pragma unroll
        for (int j = 0; j < 16; j++) {
            float pA = vA ? __expf(sAs[j] - mnewA) : 0.f;
            float pB = vB ? __expf(sBs[j] - mnewB) : 0.f;
            psA += pA; psB += pB;
            P[qa*SS + l4 + j*4] = pA;
            P[qb*SS + l4 + j*4] = pB;
        }
        psA += __shfl_xor_sync(0xffffffffu, psA, 1);
        psA += __shfl_xor_sync(0xffffffffu, psA, 2);
        psB += __shfl_xor_sync(0xffffffffu, psB, 1);
        psB += __shfl_xor_sync(0xffffffffu, psB, 2);
        lrunA = lrunA * sclA + psA;
        lrunB = lrunB * sclB + psB;
        mrunA = mnewA; mrunB = mnewB;

#pragma unroll
        for (int j = 0; j < 4; j++) {
            accrA[j].x *= sclA; accrA[j].y *= sclA; accrA[j].z *= sclA; accrA[j].w *= sclA;
            acciA[j].x *= sclA; acciA[j].y *= sclA; acciA[j].z *= sclA; acciA[j].w *= sclA;
            accrB[j].x *= sclB; accrB[j].y *= sclB; accrB[j].z *= sclB; accrB[j].w *= sclB;
            acciB[j].x *= sclB; acciB[j].y *= sclB; acciB[j].z *= sclB; acciB[j].w *= sclB;
        }
        __syncwarp();

#pragma unroll 4
        for (int k = 0; k < 64; k++) {
            float pA = P[qa*SS + k];
            float pB = P[qb*SS + k];
#pragma unroll
            for (int j = 0; j < 4; j++) {
                float4 v = *(float4*)(Vr + k*SS + l4*4 + j*16);
                accrA[j].x += pA*v.x; accrA[j].y += pA*v.y; accrA[j].z += pA*v.z; accrA[j].w += pA*v.w;
                accrB[j].x += pB*v.x; accrB[j].y += pB*v.y; accrB[j].z += pB*v.z; accrB[j].w += pB*v.w;
                float4 w = *(float4*)(Vi + k*SS + l4*4 + j*16);
                acciA[j].x += pA*w.x; acciA[j].y += pA*w.y; acciA[j].z += pA*w.z; acciA[j].w += pA*w.w;
                acciB[j].x += pB*w.x; acciB[j].y += pB*w.y; acciB[j].z += pB*w.z; acciB[j].w += pB*w.w;
            }
        }
    }

    float invA = (lrunA > 0.f) ? (1.0f / lrunA) : 0.0f;
    float invB = (lrunB > 0.f) ? (1.0f / lrunB) : 0.0f;
    float* outrA = g_Ar + (size_t)(b*NQ + q0 + qa) * OPROJ + h*DHEAD + l4*4;
    float* outiA = g_Ai + (size_t)(b*NQ + q0 + qa) * OPROJ + h*DHEAD + l4*4;
    float* outrB = g_Ar + (size_t)(b*NQ + q0 + qb) * OPROJ + h*DHEAD + l4*4;
    float* outiB = g_Ai + (size_t)(b*NQ + q0 + qb) * OPROJ + h*DHEAD + l4*4;
#pragma unroll
    for (int j = 0; j < 4; j++) {
        float4 o;
        o.x = accrA[j].x*invA; o.y = accrA[j].y*invA; o.z = accrA[j].z*invA; o.w = accrA[j].w*invA;
        *(float4*)(outrA + j*16) = o;
        o.x = acciA[j].x*invA; o.y = acciA[j].y*invA; o.z = acciA[j].z*invA; o.w = acciA[j].w*invA;
        *(float4*)(outiA + j*16) = o;
        o.x = accrB[j].x*invB; o.y = accrB[j].y*invB; o.z = accrB[j].z*invB; o.w = accrB[j].w*invB;
        *(float4*)(outrB + j*16) = o;
        o.x = acciB[j].x*invB; o.y = acciB[j].y*invB; o.z = acciB[j].z*invB; o.w = acciB[j].w*invB;
        *(float4*)(outiB + j*16) = o;
    }
}

// ---------------- launch ----------------
extern "C" void kernel_launch(void* const* d_in, const int* in_sizes, int n_in,
                              void* d_out, int out_size) {
    const float* big[6] = {0,0,0,0,0,0};
    const float* wts[8] = {0,0,0,0,0,0,0,0};
    const void*  maskp  = nullptr;
    int nbig = 0, nw = 0;
    for (int i = 0; i < n_in; i++) {
        int s = in_sizes[i];
        if (s == 1048576 && nbig < 6)    big[nbig++] = (const float*)d_in[i];
        else if (s == 131072 && nw < 8)  wts[nw++]   = (const float*)d_in[i];
        else if (s == 4096 && !maskp)    maskp       = d_in[i];
    }
    if (nbig != 6 || nw != 8) {
        for (int i = 0; i < 6; i++) big[i] = (i < n_in) ? (const float*)d_in[i] : nullptr;
        for (int i = 0; i < 8; i++) wts[i] = (6 + i < n_in) ? (const float*)d_in[6 + i] : nullptr;
        maskp = (n_in >= 15) ? d_in[14] : nullptr;
    }

    const float *Qre = big[0], *Qim = big[1], *Kre = big[2], *Kim = big[3], *Vre = big[4], *Vim = big[5];
    const float *WQr = wts[0], *WQi = wts[1], *WKr = wts[2], *WKi = wts[3];
    const float *WVr = wts[4], *WVi = wts[5], *WOr = wts[6], *WOi = wts[7];

    cudaFuncSetAttribute(attn_kernel, cudaFuncAttributeMaxDynamicSharedMemorySize, ATTN_SMEM);

    mask_kernel<<<1, 256>>>((const unsigned char*)maskp, maskp != nullptr ? 1 : 0);

    dim3 gproj(OPROJ/64, (BB*NQ)/64);
    cgemm_kernel<false><<<gproj, 256>>>(Qre, Qim, WQr, WQi, nullptr, BB*NQ,  OPROJ, RDIM, 0);
    cgemm_kernel<false><<<gproj, 256>>>(Kre, Kim, WKr, WKi, nullptr, BB*NKK, OPROJ, RDIM, 1);
    cgemm_kernel<false><<<gproj, 256>>>(Vre, Vim, WVr, WVi, nullptr, BB*NKK, OPROJ, RDIM, 2);

    dim3 gattn(NQ/128, BH);
    attn_kernel<<<gattn, 256, ATTN_SMEM>>>();

    dim3 gout(RDIM/64, (BB*NQ)/64);
    if (out_size == 2097152)
        cgemm_kernel<false><<<gout, 256>>>(nullptr, nullptr, WOr, WOi, (float*)d_out, BB*NQ, RDIM, OPROJ, 3);
    else
        cgemm_kernel<true ><<<gout, 256>>>(nullptr, nullptr, WOr, WOi, (float*)d_out, BB*NQ, RDIM, OPROJ, 3);
}

// round 17
// speedup vs baseline: 2.7977x; 1.3663x over previous
#include <cuda_runtime.h>
#include <math.h>

// Problem constants
#define BB     4
#define NQ     1024
#define NKK    1024
#define RDIM   256
#define NHH    8
#define DHEAD  64
#define BH     (BB*NHH)      // 32
#define OPROJ  (NHH*DHEAD)   // 512

// ---------------- scratch (static device globals; no allocations) ----------------
__device__ __align__(256) float g_Qpr[BH*NQ*DHEAD];
__device__ __align__(256) float g_Qpi[BH*NQ*DHEAD];
__device__ __align__(256) float g_Kpr[BH*NKK*DHEAD];
__device__ __align__(256) float g_Kpi[BH*NKK*DHEAD];
__device__ __align__(256) float g_Vpr[BH*NKK*DHEAD];
__device__ __align__(256) float g_Vpi[BH*NKK*DHEAD];
__device__ __align__(256) float g_Ar [BB*NQ*OPROJ];
__device__ __align__(256) float g_Ai [BB*NQ*OPROJ];
__device__ __align__(256) float g_maskb[BB*NKK];

// ---- tf32 helpers ----
__device__ __forceinline__ float tf32r(float x) {
    unsigned u; asm("cvt.rna.tf32.f32 %0, %1;" : "=r"(u) : "f"(x));
    return __uint_as_float(u);
}
__device__ __forceinline__ void mma_tf32(float c[4],
    unsigned a0, unsigned a1, unsigned a2, unsigned a3,
    unsigned b0, unsigned b1)
{
    asm("mma.sync.aligned.m16n8k8.row.col.f32.tf32.tf32.f32 "
        "{%0,%1,%2,%3}, {%4,%5,%6,%7}, {%8,%9}, {%0,%1,%2,%3};"
        : "+f"(c[0]), "+f"(c[1]), "+f"(c[2]), "+f"(c[3])
        : "r"(a0), "r"(a1), "r"(a2), "r"(a3), "r"(b0), "r"(b1));
}

// ---------------- mask sniff + convert (uint8 / int32 / f32 / bf16) ----------------
__global__ void mask_kernel(const unsigned char* __restrict__ mp, int present) {
    __shared__ int s_flags;
    if (threadIdx.x == 0) s_flags = 0;
    __syncthreads();
    if (!present) {
        for (int k = threadIdx.x; k < BB*NKK; k += blockDim.x) g_maskb[k] = 0.0f;
        return;
    }
    int f = 0;
    for (int i = threadIdx.x; i < BB*NKK; i += blockDim.x) {
        unsigned char v = mp[i];
        if (v) {
            int p = i & 3;
            if (v == 0x3F)      { if (p == 1) f |= 2;  else if (p == 3) f |= 4;  else f |= 1; }
            else if (v == 0x80) { if (p == 0) f |= 8;  else if (p == 2) f |= 16; else f |= 1; }
            else                { if (p != 0) f |= 1;  else f |= 32; }
        }
    }
    if (f) atomicOr(&s_flags, f);
    __syncthreads();
    int F = s_flags;
    int mode;
    if      (F & (2|8))  mode = 3;
    else if (F & (4|16)) mode = 2;
    else if (F & 1)      mode = 0;
    else if (F & 32)     mode = 1;
    else                 mode = 0;

    for (int k = threadIdx.x; k < BB*NKK; k += blockDim.x) {
        bool m;
        if      (mode == 0) m = mp[k] != 0;
        else if (mode == 1) m = ((const int*)mp)[k] != 0;
        else if (mode == 2) m = ((const float*)mp)[k] != 0.0f;
        else                m = ((const unsigned short*)mp)[k] != 0;
        g_maskb[k] = m ? 0.0f : -1e30f;
    }
}

// ---------------- complex GEMM v4 (R16 proven): tf32 mma.sync, double-buffered ----------------
#define TW 20
template<bool REAL_ONLY>
__global__ __launch_bounds__(256) void cgemm_kernel(
    const float* __restrict__ Xr, const float* __restrict__ Xi,
    const float* __restrict__ Wr, const float* __restrict__ Wi,
    float* __restrict__ Oc, int M, int N, int K, int which)
{
    __shared__ float Xs_r[2][64][TW], Xs_i[2][64][TW];
    __shared__ float Ws_r[2][64][TW], Ws_i[2][64][TW];

    float* Or = nullptr; float* Oi = nullptr;
    if (which == 0)      { Or = g_Qpr; Oi = g_Qpi; }
    else if (which == 1) { Or = g_Kpr; Oi = g_Kpi; }
    else if (which == 2) { Or = g_Vpr; Oi = g_Vpi; }
    else                 { Xr = g_Ar;  Xi = g_Ai;  }

    int tid = threadIdx.x;
    int m0 = blockIdx.y * 64, n0 = blockIdx.x * 64;
    int lrow = tid >> 2, lc = (tid & 3) * 4;

    int warp = tid >> 5, lane = tid & 31;
    int gid = lane >> 2, tig = lane & 3;
    int m0w = (warp >> 1) * 16;
    int n0w = (warp & 1) * 32;

    float accRe[4][4], accIm[4][4];
#pragma unroll
    for (int t = 0; t < 4; t++)
#pragma unroll
        for (int c = 0; c < 4; c++) { accRe[t][c] = 0.f; if (!REAL_ONLY) accIm[t][c] = 0.f; }

    const float* xr_p = Xr + (size_t)(m0 + lrow) * K + lc;
    const float* xi_p = Xi + (size_t)(m0 + lrow) * K + lc;
    const float* wr_p = Wr + (size_t)(n0 + lrow) * K + lc;
    const float* wi_p = Wi + (size_t)(n0 + lrow) * K + lc;

    int NK = K >> 4;

    float4 xr = *(const float4*)(xr_p);
    float4 xi = *(const float4*)(xi_p);
    float4 wr = *(const float4*)(wr_p);
    float4 wi = *(const float4*)(wi_p);
    {
        Xs_r[0][lrow][lc  ] = tf32r(xr.x); Xs_r[0][lrow][lc+1] = tf32r(xr.y);
        Xs_r[0][lrow][lc+2] = tf32r(xr.z); Xs_r[0][lrow][lc+3] = tf32r(xr.w);
        Xs_i[0][lrow][lc  ] = tf32r(xi.x); Xs_i[0][lrow][lc+1] = tf32r(xi.y);
        Xs_i[0][lrow][lc+2] = tf32r(xi.z); Xs_i[0][lrow][lc+3] = tf32r(xi.w);
        Ws_r[0][lrow][lc  ] = tf32r(wr.x); Ws_r[0][lrow][lc+1] = tf32r(wr.y);
        Ws_r[0][lrow][lc+2] = tf32r(wr.z); Ws_r[0][lrow][lc+3] = tf32r(wr.w);
        Ws_i[0][lrow][lc  ] = tf32r(wi.x); Ws_i[0][lrow][lc+1] = tf32r(wi.y);
        Ws_i[0][lrow][lc+2] = tf32r(wi.z); Ws_i[0][lrow][lc+3] = tf32r(wi.w);
    }
    __syncthreads();

    int pb = 0;
    for (int kt = 0; kt < NK; kt++) {
        if (kt + 1 < NK) {
            int k0 = (kt + 1) << 4;
            xr = *(const float4*)(xr_p + k0);
            xi = *(const float4*)(xi_p + k0);
            wr = *(const float4*)(wr_p + k0);
            wi = *(const float4*)(wi_p + k0);
        }
#pragma unroll
        for (int ks = 0; ks < 16; ks += 8) {
            unsigned ar0 = __float_as_uint(Xs_r[pb][m0w+gid  ][ks+tig  ]);
            unsigned ar1 = __float_as_uint(Xs_r[pb][m0w+gid+8][ks+tig  ]);
            unsigned ar2 = __float_as_uint(Xs_r[pb][m0w+gid  ][ks+tig+4]);
            unsigned ar3 = __float_as_uint(Xs_r[pb][m0w+gid+8][ks+tig+4]);
            unsigned ai0 = __float_as_uint(Xs_i[pb][m0w+gid  ][ks+tig  ]);
            unsigned ai1 = __float_as_uint(Xs_i[pb][m0w+gid+8][ks+tig  ]);
            unsigned ai2 = __float_as_uint(Xs_i[pb][m0w+gid  ][ks+tig+4]);
            unsigned ai3 = __float_as_uint(Xs_i[pb][m0w+gid+8][ks+tig+4]);
#pragma unroll
            for (int t = 0; t < 4; t++) {
                int n = n0w + t*8 + gid;
                unsigned br0 = __float_as_uint(Ws_r[pb][n][ks+tig  ]);
                unsigned br1 = __float_as_uint(Ws_r[pb][n][ks+tig+4]);
                float bi0f = Ws_i[pb][n][ks+tig  ];
                float bi1f = Ws_i[pb][n][ks+tig+4];
                unsigned nbi0 = __float_as_uint(-bi0f);
                unsigned nbi1 = __float_as_uint(-bi1f);
                mma_tf32(accRe[t], ar0,ar1,ar2,ar3, br0,br1);
                mma_tf32(accRe[t], ai0,ai1,ai2,ai3, nbi0,nbi1);
                if (!REAL_ONLY) {
                    unsigned bi0 = __float_as_uint(bi0f);
                    unsigned bi1 = __float_as_uint(bi1f);
                    mma_tf32(accIm[t], ar0,ar1,ar2,ar3, bi0,bi1);
                    mma_tf32(accIm[t], ai0,ai1,ai2,ai3, br0,br1);
                }
            }
        }
        __syncthreads();
        if (kt + 1 < NK) {
            int nb = pb ^ 1;
            Xs_r[nb][lrow][lc  ] = tf32r(xr.x); Xs_r[nb][lrow][lc+1] = tf32r(xr.y);
            Xs_r[nb][lrow][lc+2] = tf32r(xr.z); Xs_r[nb][lrow][lc+3] = tf32r(xr.w);
            Xs_i[nb][lrow][lc  ] = tf32r(xi.x); Xs_i[nb][lrow][lc+1] = tf32r(xi.y);
            Xs_i[nb][lrow][lc+2] = tf32r(xi.z); Xs_i[nb][lrow][lc+3] = tf32r(xi.w);
            Ws_r[nb][lrow][lc  ] = tf32r(wr.x); Ws_r[nb][lrow][lc+1] = tf32r(wr.y);
            Ws_r[nb][lrow][lc+2] = tf32r(wr.z); Ws_r[nb][lrow][lc+3] = tf32r(wr.w);
            Ws_i[nb][lrow][lc  ] = tf32r(wi.x); Ws_i[nb][lrow][lc+1] = tf32r(wi.y);
            Ws_i[nb][lrow][lc+2] = tf32r(wi.z); Ws_i[nb][lrow][lc+3] = tf32r(wi.w);
            __syncthreads();
        }
        pb ^= 1;
    }

#pragma unroll
    for (int t = 0; t < 4; t++) {
#pragma unroll
        for (int c = 0; c < 4; c++) {
            int mrow = m0 + m0w + gid + ((c & 2) ? 8 : 0);
            int o    = n0 + n0w + t*8 + 2*tig + (c & 1);
            float re = accRe[t][c];
            if (which != 3) {
                float im = accIm[t][c];
                int b = mrow >> 10, n = mrow & 1023;
                int h = o >> 6,  d = o & 63;
                size_t idx = ((size_t)(b*NHH + h) * NQ + n) * 64 + d;
                Or[idx] = re;
                Oi[idx] = im;
            } else if (REAL_ONLY) {
                Oc[(size_t)mrow * N + o] = re;
            } else {
                size_t base = ((size_t)mrow * N + o) * 2;
                Oc[base] = re; Oc[base+1] = accIm[t][c];
            }
        }
    }
}

// ---------------- fused attention v5: tf32 mma scores AND tf32 mma AV ----------------
// Smem: Qr,Qi 128xSS | Kr,Ki 64xSS | Vtr,Vti 64xSS TRANSPOSED [d][k] | P 128xSS | Mb 64 | Sc 128
#define SS 68
#define ATTN_SMEM ((640*SS + 192) * 4)   // 174,848 B

__global__ __launch_bounds__(256, 1) void attn_kernel() {
    extern __shared__ float sm[];
    float* Qr  = sm;
    float* Qi  = Qr  + 128*SS;
    float* Kr  = Qi  + 128*SS;
    float* Ki  = Kr  + 64*SS;
    float* Vtr = Ki  + 64*SS;
    float* Vti = Vtr + 64*SS;
    float* P   = Vti + 64*SS;
    float* Mb  = P   + 128*SS;
    float* Sc  = Mb  + 64;      // per-row scale / inv-l (128)

    int tid = threadIdx.x;
    int bh  = blockIdx.y;
    int b   = bh >> 3;
    int h   = bh & 7;
    int q0  = blockIdx.x * 128;

    int warp = tid >> 5, lane = tid & 31;
    int gid  = lane >> 2, tig = lane & 3;
    int m0w  = warp * 16;

    int qa = tid >> 2;        // quad softmax rows
    int qb = qa + 64;
    int l4 = tid & 3;

    const float* Qpr = g_Qpr + ((size_t)bh * NQ + q0) * 64;
    const float* Qpi = g_Qpi + ((size_t)bh * NQ + q0) * 64;
    for (int t = tid; t < 128*16; t += 256) {
        int r = t >> 4, c = (t & 15) * 4;
        float4 v = *(const float4*)(Qpr + r*64 + c);
        v.x = tf32r(v.x); v.y = tf32r(v.y); v.z = tf32r(v.z); v.w = tf32r(v.w);
        *(float4*)(Qr + r*SS + c) = v;
        v = *(const float4*)(Qpi + r*64 + c);
        v.x = tf32r(v.x); v.y = tf32r(v.y); v.z = tf32r(v.z); v.w = tf32r(v.w);
        *(float4*)(Qi + r*SS + c) = v;
    }

    const float* Kbr = g_Kpr + (size_t)bh * NKK * 64;
    const float* Kbi = g_Kpi + (size_t)bh * NKK * 64;
    const float* Vbr = g_Vpr + (size_t)bh * NKK * 64;
    const float* Vbi = g_Vpi + (size_t)bh * NKK * 64;

    float mrunA = -1e30f, lrunA = 0.f;
    float mrunB = -1e30f, lrunB = 0.f;

    // AV accumulators in mma fragment layout: 8 d-tiles x c[4], re/im
    float avr[8][4], avi[8][4];
#pragma unroll
    for (int t = 0; t < 8; t++)
#pragma unroll
        for (int c = 0; c < 4; c++) { avr[t][c] = 0.f; avi[t][c] = 0.f; }

    for (int kt = 0; kt < NKK/64; kt++) {
        int k0 = kt * 64;
        __syncthreads();
        for (int t = tid; t < 64*16; t += 256) {
            int r = t >> 4, c = (t & 15) * 4;   // r = k row, c = d base
            float4 v = *(const float4*)(Kbr + (size_t)(k0+r)*64 + c);
            v.x = tf32r(v.x); v.y = tf32r(v.y); v.z = tf32r(v.z); v.w = tf32r(v.w);
            *(float4*)(Kr + r*SS + c) = v;
            v = *(const float4*)(Kbi + (size_t)(k0+r)*64 + c);
            v.x = tf32r(v.x); v.y = tf32r(v.y); v.z = tf32r(v.z); v.w = tf32r(v.w);
            *(float4*)(Ki + r*SS + c) = v;
            // V transposed: Vt[d][k]
            v = *(const float4*)(Vbr + (size_t)(k0+r)*64 + c);
            Vtr[(c  )*SS + r] = tf32r(v.x);
            Vtr[(c+1)*SS + r] = tf32r(v.y);
            Vtr[(c+2)*SS + r] = tf32r(v.z);
            Vtr[(c+3)*SS + r] = tf32r(v.w);
            v = *(const float4*)(Vbi + (size_t)(k0+r)*64 + c);
            Vti[(c  )*SS + r] = tf32r(v.x);
            Vti[(c+1)*SS + r] = tf32r(v.y);
            Vti[(c+2)*SS + r] = tf32r(v.z);
            Vti[(c+3)*SS + r] = tf32r(v.w);
        }
        if (tid < 64) Mb[tid] = g_maskb[b*NKK + k0 + tid];
        __syncthreads();

        // ---- scores via tf32 mma: warp owns 16 q rows x 64 k
        float accRe[8][4], accIm[8][4];
#pragma unroll
        for (int n = 0; n < 8; n++)
#pragma unroll
            for (int c = 0; c < 4; c++) { accRe[n][c] = 0.f; accIm[n][c] = 0.f; }

#pragma unroll
        for (int d = 0; d < 64; d += 8) {
            const float* qrp = Qr + (m0w + gid)*SS + d + tig;
            const float* qip = Qi + (m0w + gid)*SS + d + tig;
            unsigned ar0 = __float_as_uint(qrp[0]);
            unsigned ar1 = __float_as_uint(qrp[8*SS]);
            unsigned ar2 = __float_as_uint(qrp[4]);
            unsigned ar3 = __float_as_uint(qrp[8*SS + 4]);
            unsigned ai0 = __float_as_uint(qip[0]);
            unsigned ai1 = __float_as_uint(qip[8*SS]);
            unsigned ai2 = __float_as_uint(qip[4]);
            unsigned ai3 = __float_as_uint(qip[8*SS + 4]);
#pragma unroll
            for (int n = 0; n < 8; n++) {
                int kk = n*8 + gid;
                const float* krp = Kr + kk*SS + d + tig;
                const float* kip = Ki + kk*SS + d + tig;
                unsigned br0 = __float_as_uint(krp[0]);
                unsigned br1 = __float_as_uint(krp[4]);
                float bi0f = kip[0], bi1f = kip[4];
                unsigned bi0  = __float_as_uint(bi0f);
                unsigned bi1  = __float_as_uint(bi1f);
                unsigned nbi0 = __float_as_uint(-bi0f);
                unsigned nbi1 = __float_as_uint(-bi1f);
                mma_tf32(accRe[n], ar0,ar1,ar2,ar3, br0,br1);
                mma_tf32(accRe[n], ai0,ai1,ai2,ai3, bi0,bi1);
                mma_tf32(accIm[n], ai0,ai1,ai2,ai3, br0,br1);
                mma_tf32(accIm[n], ar0,ar1,ar2,ar3, nbi0,nbi1);
            }
        }

        // |s|*scale + mask -> P (logits)
        {
            int r0 = m0w + gid, r1 = r0 + 8;
#pragma unroll
            for (int n = 0; n < 8; n++) {
                int kc = n*8 + tig*2;
                float mb0 = Mb[kc], mb1 = Mb[kc+1];
                P[r0*SS + kc  ] = sqrtf(accRe[n][0]*accRe[n][0] + accIm[n][0]*accIm[n][0]) * 0.125f + mb0;
                P[r0*SS + kc+1] = sqrtf(accRe[n][1]*accRe[n][1] + accIm[n][1]*accIm[n][1]) * 0.125f + mb1;
                P[r1*SS + kc  ] = sqrtf(accRe[n][2]*accRe[n][2] + accIm[n][2]*accIm[n][2]) * 0.125f + mb0;
                P[r1*SS + kc+1] = sqrtf(accRe[n][3]*accRe[n][3] + accIm[n][3]*accIm[n][3]) * 0.125f + mb1;
            }
        }
        __syncthreads();

        // ---- online softmax (quad layout): logits -> tf32 probs in P, scale in Sc
        float sAs[16], sBs[16];
        float lmA = -1e30f, lmB = -1e30f;
#pragma unroll
        for (int j = 0; j < 16; j++) {
            sAs[j] = P[qa*SS + l4 + j*4];
            sBs[j] = P[qb*SS + l4 + j*4];
            lmA = fmaxf(lmA, sAs[j]);
            lmB = fmaxf(lmB, sBs[j]);
        }
        lmA = fmaxf(lmA, __shfl_xor_sync(0xffffffffu, lmA, 1));
        lmA = fmaxf(lmA, __shfl_xor_sync(0xffffffffu, lmA, 2));
        lmB = fmaxf(lmB, __shfl_xor_sync(0xffffffffu, lmB, 1));
        lmB = fmaxf(lmB, __shfl_xor_sync(0xffffffffu, lmB, 2));
        float mnewA = fmaxf(mrunA, lmA);
        float mnewB = fmaxf(mrunB, lmB);
        bool vA = (mnewA > -1e29f), vB = (mnewB > -1e29f);
        float sclA = vA ? __expf(mrunA - mnewA) : 1.0f;
        float sclB = vB ? __expf(mrunB - mnewB) : 1.0f;

        float psA = 0.f, psB = 0.f;
#pragma unroll
        for (int j = 0; j < 16; j++) {
            float pA = vA ? tf32r(__expf(sAs[j] - mnewA)) : 0.f;
            float pB = vB ? tf32r(__expf(sBs[j] - mnewB)) : 0.f;
            psA += pA; psB += pB;
            P[qa*SS + l4 + j*4] = pA;
            P[qb*SS + l4 + j*4] = pB;
        }
        psA += __shfl_xor_sync(0xffffffffu, psA, 1);
        psA += __shfl_xor_sync(0xffffffffu, psA, 2);
        psB += __shfl_xor_sync(0xffffffffu, psB, 1);
        psB += __shfl_xor_sync(0xffffffffu, psB, 2);
        lrunA = lrunA * sclA + psA;
        lrunB = lrunB * sclB + psB;
        mrunA = mnewA; mrunB = mnewB;
        Sc[qa] = sclA;           // 4 threads write identical value
        Sc[qb] = sclB;
        __syncthreads();

        // ---- AV via tf32 mma: scale frags by Sc, then P(128xk) @ Vt^T
        {
            float s0 = Sc[m0w + gid], s1 = Sc[m0w + gid + 8];
#pragma unroll
            for (int t = 0; t < 8; t++) {
                avr[t][0] *= s0; avr[t][1] *= s0; avr[t][2] *= s1; avr[t][3] *= s1;
                avi[t][0] *= s0; avi[t][1] *= s0; avi[t][2] *= s1; avi[t][3] *= s1;
            }
        }
#pragma unroll
        for (int k8 = 0; k8 < 64; k8 += 8) {
            const float* pp = P + (m0w + gid)*SS + k8 + tig;
            unsigned a0 = __float_as_uint(pp[0]);
            unsigned a1 = __float_as_uint(pp[8*SS]);
            unsigned a2 = __float_as_uint(pp[4]);
            unsigned a3 = __float_as_uint(pp[8*SS + 4]);
#pragma unroll
            for (int t = 0; t < 8; t++) {
                int dd = t*8 + gid;
                const float* vr = Vtr + dd*SS + k8 + tig;
                const float* vi = Vti + dd*SS + k8 + tig;
                unsigned br0 = __float_as_uint(vr[0]);
                unsigned br1 = __float_as_uint(vr[4]);
                unsigned bi0 = __float_as_uint(vi[0]);
                unsigned bi1 = __float_as_uint(vi[4]);
                mma_tf32(avr[t], a0,a1,a2,a3, br0,br1);
                mma_tf32(avi[t], a0,a1,a2,a3, bi0,bi1);
            }
        }
    }

    // ---- epilogue: per-row 1/l via Sc, write planar attn output from fragments
    {
        float invA = (lrunA > 0.f) ? (1.0f / lrunA) : 0.0f;
        float invB = (lrunB > 0.f) ? (1.0f / lrunB) : 0.0f;
        __syncthreads();
        Sc[qa] = invA;
        Sc[qb] = invB;
        __syncthreads();
    }
    {
        float i0 = Sc[m0w + gid], i1 = Sc[m0w + gid + 8];
        int row0 = q0 + m0w + gid, row1 = row0 + 8;
        float* or0 = g_Ar + (size_t)(b*NQ + row0) * OPROJ + h*DHEAD;
        float* oi0 = g_Ai + (size_t)(b*NQ + row0) * OPROJ + h*DHEAD;
        float* or1 = g_Ar + (size_t)(b*NQ + row1) * OPROJ + h*DHEAD;
        float* oi1 = g_Ai + (size_t)(b*NQ + row1) * OPROJ + h*DHEAD;
#pragma unroll
        for (int t = 0; t < 8; t++) {
            int d0 = t*8 + 2*tig;
            or0[d0]   = avr[t][0]*i0;  or0[d0+1] = avr[t][1]*i0;
            or1[d0]   = avr[t][2]*i1;  or1[d0+1] = avr[t][3]*i1;
            oi0[d0]   = avi[t][0]*i0;  oi0[d0+1] = avi[t][1]*i0;
            oi1[d0]   = avi[t][2]*i1;  oi1[d0+1] = avi[t][3]*i1;
        }
    }
}

// ---------------- launch ----------------
extern "C" void kernel_launch(void* const* d_in, const int* in_sizes, int n_in,
                              void* d_out, int out_size) {
    const float* big[6] = {0,0,0,0,0,0};
    const float* wts[8] = {0,0,0,0,0,0,0,0};
    const void*  maskp  = nullptr;
    int nbig = 0, nw = 0;
    for (int i = 0; i < n_in; i++) {
        int s = in_sizes[i];
        if (s == 1048576 && nbig < 6)    big[nbig++] = (const float*)d_in[i];
        else if (s == 131072 && nw < 8)  wts[nw++]   = (const float*)d_in[i];
        else if (s == 4096 && !maskp)    maskp       = d_in[i];
    }
    if (nbig != 6 || nw != 8) {
        for (int i = 0; i < 6; i++) big[i] = (i < n_in) ? (const float*)d_in[i] : nullptr;
        for (int i = 0; i < 8; i++) wts[i] = (6 + i < n_in) ? (const float*)d_in[6 + i] : nullptr;
        maskp = (n_in >= 15) ? d_in[14] : nullptr;
    }

    const float *Qre = big[0], *Qim = big[1], *Kre = big[2], *Kim = big[3], *Vre = big[4], *Vim = big[5];
    const float *WQr = wts[0], *WQi = wts[1], *WKr = wts[2], *WKi = wts[3];
    const float *WVr = wts[4], *WVi = wts[5], *WOr = wts[6], *WOi = wts[7];

    cudaFuncSetAttribute(attn_kernel, cudaFuncAttributeMaxDynamicSharedMemorySize, ATTN_SMEM);

    mask_kernel<<<1, 256>>>((const unsigned char*)maskp, maskp != nullptr ? 1 : 0);

    dim3 gproj(OPROJ/64, (BB*NQ)/64);
    cgemm_kernel<false><<<gproj, 256>>>(Qre, Qim, WQr, WQi, nullptr, BB*NQ,  OPROJ, RDIM, 0);
    cgemm_kernel<false><<<gproj, 256>>>(Kre, Kim, WKr, WKi, nullptr, BB*NKK, OPROJ, RDIM, 1);
    cgemm_kernel<false><<<gproj, 256>>>(Vre, Vim, WVr, WVi, nullptr, BB*NKK, OPROJ, RDIM, 2);

    dim3 gattn(NQ/128, BH);
    attn_kernel<<<gattn, 256, ATTN_SMEM>>>();

    dim3 gout(RDIM/64, (BB*NQ)/64);
    if (out_size == 2097152)
        cgemm_kernel<false><<<gout, 256>>>(nullptr, nullptr, WOr, WOi, (float*)d_out, BB*NQ, RDIM, OPROJ, 3);
    else
        cgemm_kernel<true ><<<gout, 256>>>(nullptr, nullptr, WOr, WOi, (float*)d_out, BB*NQ, RDIM, OPROJ, 3);
}